// round 12
// baseline (speedup 1.0000x reference)
#include <cuda_runtime.h>
#include <cuda_bf16.h>
#include <cuda_fp16.h>
#include <math.h>
#include <stdint.h>

#define NN 20480
#define EE 327680
#define GG 64
#define HD 256     // H*D
#define HH 4
#define DD 64
#define CC 10
#define NPG (NN/GG)

// ---------------- scratch (static device globals; no allocation) ----------------
__device__ __nv_bfloat16 g_zb[NN*HD];        // z in bf16 (agg gather operand)
__device__ float g_hA[NN*HD];
__device__ float g_hB[NN*HD];
__device__ float g_el[NN*HH];
__device__ float g_er[NN*HH];
__device__ unsigned g_elmaxU[3*HH];          // encoded per-head el max, per layer
__device__ int   g_deg[NN];
__device__ int   g_rowptr[NN+1];
__device__ int   g_cursor[NN];
__device__ int   g_esrc[EE];
__device__ __half g_af16[NN*HD];             // GEMM A operand (fp16)
__device__ __half g_bf16[3][HD*HD];          // W per layer: [K][256] fp16

__device__ __forceinline__ float lrelu(float x) { return x > 0.f ? x : 0.2f * x; }
__device__ __forceinline__ float elu1 (float x) { return x > 0.f ? x : expm1f(x); }

// monotone float<->uint encoding for atomicMax on floats
__device__ __forceinline__ unsigned fenc(float f) {
    unsigned u = __float_as_uint(f);
    return (u & 0x80000000u) ? ~u : (u | 0x80000000u);
}
__device__ __forceinline__ float fdec(unsigned u) {
    return (u & 0x80000000u) ? __uint_as_float(u & 0x7fffffffu) : __uint_as_float(~u);
}
__device__ __forceinline__ unsigned h2_bits(__half2 h) {
    return *reinterpret_cast<unsigned*>(&h);
}
// exact bf16 pair -> two f32 (2 inst)
__device__ __forceinline__ void bf2f(unsigned r, float& lo, float& hi) {
    lo = __uint_as_float(r << 16);
    hi = __uint_as_float(r & 0xffff0000u);
}

__device__ __forceinline__ uint32_t smem_u32(const void* p) {
    uint32_t a;
    asm("{ .reg .u64 t; cvta.to.shared.u64 t, %1; cvt.u32.u64 %0, t; }" : "=r"(a) : "l"(p));
    return a;
}
__device__ __forceinline__ void ldmat4(uint32_t* r, uint32_t a) {
    asm volatile("ldmatrix.sync.aligned.m8n8.x4.shared.b16 {%0,%1,%2,%3}, [%4];"
        : "=r"(r[0]), "=r"(r[1]), "=r"(r[2]), "=r"(r[3]) : "r"(a));
}
__device__ __forceinline__ void ldmat4t(uint32_t* r, uint32_t a) {
    asm volatile("ldmatrix.sync.aligned.m8n8.x4.trans.shared.b16 {%0,%1,%2,%3}, [%4];"
        : "=r"(r[0]), "=r"(r[1]), "=r"(r[2]), "=r"(r[3]) : "r"(a));
}
__device__ __forceinline__ void mma16816h(float* c, const uint32_t* a, const uint32_t* b) {
    asm volatile(
        "mma.sync.aligned.m16n8k16.row.col.f32.f16.f16.f32 "
        "{%0,%1,%2,%3}, {%4,%5,%6,%7}, {%8,%9}, {%0,%1,%2,%3};"
        : "+f"(c[0]), "+f"(c[1]), "+f"(c[2]), "+f"(c[3])
        : "r"(a[0]), "r"(a[1]), "r"(a[2]), "r"(a[3]), "r"(b[0]), "r"(b[1]));
}
#define CP16(s, g) asm volatile("cp.async.cg.shared.global [%0], [%1], 16;" \
    :: "r"(s), "l"(__cvta_generic_to_global(g)))
#define CP_COMMIT() asm volatile("cp.async.commit_group;" ::: "memory")
#define CP_WAIT0()  asm volatile("cp.async.wait_group 0;" ::: "memory")
#define CP_WAIT1()  asm volatile("cp.async.wait_group 1;" ::: "memory")

// ---------------- CSR build ----------------
__global__ void zero_deg_kernel() {
    int i = blockIdx.x * blockDim.x + threadIdx.x;
    if (i < NN) g_deg[i] = 0;
}
__global__ void hist_kernel(const int* __restrict__ dst) {
    int i = blockIdx.x * blockDim.x + threadIdx.x;
    if (i < EE) atomicAdd(&g_deg[dst[i]], 1);
}
__global__ void scan_kernel() {
    __shared__ int part[512];
    const int CH = NN / 512;
    int t = threadIdx.x;
    int s = 0;
    for (int i = 0; i < CH; i++) s += g_deg[t*CH + i];
    part[t] = s;
    __syncthreads();
    if (t == 0) {
        int r = 0;
        for (int i = 0; i < 512; i++) { int v = part[i]; part[i] = r; r += v; }
        g_rowptr[NN] = r;
    }
    __syncthreads();
    int run = part[t];
    for (int i = 0; i < CH; i++) {
        int idx = t*CH + i;
        g_rowptr[idx] = run;
        g_cursor[idx] = run;
        run += g_deg[idx];
    }
}
__global__ void scatter_kernel(const int* __restrict__ src, const int* __restrict__ dst) {
    int i = blockIdx.x * blockDim.x + threadIdx.x;
    if (i < EE) {
        int p = atomicAdd(&g_cursor[dst[i]], 1);
        g_esrc[p] = src[i];
    }
}

// ---------------- conversions: x -> fp16 A, W0..W2 -> fp16 B, elmax reset ----------------
__global__ void conv_kernel(const float* __restrict__ x,
                            const float* __restrict__ W0,
                            const float* __restrict__ W1,
                            const float* __restrict__ W2) {
    int i = blockIdx.x * blockDim.x + threadIdx.x;
    if (blockIdx.x == 0 && threadIdx.x < 3 * HH) g_elmaxU[threadIdx.x] = 0u;
    const int NX4 = NN * 128 / 4;   // x as float4
    if (i < NX4) {
        float4 v = ((const float4*)x)[i];
        ((__half2*)g_af16)[2*i]   = __floats2half2_rn(v.x, v.y);
        ((__half2*)g_af16)[2*i+1] = __floats2half2_rn(v.z, v.w);
        return;
    }
    int j = i - NX4;
    const float* B; int layer, off;
    if (j < 128 * HD)           { B = W0; layer = 0; off = j; }
    else if (j < (128+256)*HD)  { B = W1; layer = 1; off = j - 128 * HD; }
    else if (j < (128+512)*HD)  { B = W2; layer = 2; off = j - (128+256) * HD; }
    else return;
    g_bf16[layer][off] = __float2half(B[off]);
}

// ---------------- fp16 mma.sync GEMM + fused attn projections + fused el-max ----------------
// CTA 64(M)x128(N), 8 warps (warp = 16x64), K chunks of 32, cp.async double buffer.
#define ARB 80        // A smem row bytes (32 fp16 = 64B + pad)
#define BRB 272       // B smem row bytes (128 fp16 = 256B + pad)
#define S_B   5120    // 64 rows * ARB
#define BUF   13824   // S_B + 32*BRB
#define SMEM_GEMM (2*BUF)

__global__ __launch_bounds__(256, 4) void gemm_mma_kernel(
    const __half* __restrict__ A, const __half* __restrict__ B,
    __nv_bfloat16* __restrict__ Zb, unsigned* __restrict__ elmaxU,
    const float* __restrict__ al, const float* __restrict__ ar, int K) {
    extern __shared__ char sm[];
    uint32_t sb = smem_u32(sm);
    int tid = threadIdx.x, lane = tid & 31, wid = tid >> 5;
    int wm = wid & 3, wn = wid >> 2;
    int bm = blockIdx.x * 64, bn = blockIdx.y * 128;

    float acc[8][4];
#pragma unroll
    for (int j = 0; j < 8; j++)
#pragma unroll
        for (int q = 0; q < 4; q++) acc[j][q] = 0.f;

    auto issue = [&](int c, int buf) {
        int k0 = c * 32;
        uint32_t s0 = sb + buf * BUF;
        {
            int arow = tid >> 2, ach = tid & 3;
            const __half* ga = A + (size_t)(bm + arow) * K + k0 + ach * 8;
            CP16(s0 + arow * ARB + ach * 16, ga);
        }
#pragma unroll
        for (int r = 0; r < 2; r++) {
            int idx  = tid + r * 256;
            int brow = idx >> 4, bch = idx & 15;
            const __half* gb = B + (size_t)(k0 + brow) * HD + bn + bch * 8;
            CP16(s0 + S_B + brow * BRB + bch * 16, gb);
        }
    };

    auto compute = [&](int buf) {
        uint32_t s0 = sb + buf * BUF;
#pragma unroll
        for (int ks = 0; ks < 32; ks += 16) {
            uint32_t ah[4];
            {
                int row = wm * 16 + (lane & 15);
                uint32_t ad = s0 + row * ARB + (ks + (lane >> 4) * 8) * 2;
                ldmat4(ah, ad);
            }
#pragma unroll
            for (int jj = 0; jj < 4; jj++) {
                int krow = ks + (lane & 15);
                int ncol = wn * 64 + jj * 16 + (lane >> 4) * 8;
                uint32_t bd = s0 + S_B + krow * BRB + ncol * 2;
                uint32_t bh[4];
                ldmat4t(bh, bd);
                mma16816h(acc[2*jj],   ah, bh);
                mma16816h(acc[2*jj+1], ah, bh + 2);
            }
        }
    };

    int nch = K >> 5;
    issue(0, 0);
    CP_COMMIT();
    for (int c = 0; c < nch; c++) {
        if (c + 1 < nch) {
            issue(c + 1, (c + 1) & 1);
            CP_COMMIT();
            CP_WAIT1();
        } else {
            CP_WAIT0();
        }
        __syncthreads();
        compute(c & 1);
        __syncthreads();
    }

    int grp = lane >> 2, tig = lane & 3;

    // ---- store z as bf16 (rows bm+wm*16+grp and +8) ----
    {
        int rbase = bm + wm * 16 + grp;
#pragma unroll
        for (int j = 0; j < 8; j++) {
            int col = bn + wn * 64 + j * 8 + tig * 2;
            __nv_bfloat162 b0 = __floats2bfloat162_rn(acc[j][0], acc[j][1]);
            __nv_bfloat162 b1 = __floats2bfloat162_rn(acc[j][2], acc[j][3]);
            *(__nv_bfloat162*)(Zb + (size_t)rbase * HD + col)       = b0;
            *(__nv_bfloat162*)(Zb + (size_t)(rbase + 8) * HD + col) = b1;
        }
    }

    {   // ---- fused el/er for head hglob + global el-max atomic ----
        int hglob = (bn >> 6) + wn;
        const float* alh = al + hglob * DD;
        const float* arh = ar + hglob * DD;
        float alv[16], arv[16];
#pragma unroll
        for (int j = 0; j < 8; j++) {
            int cw = j * 8 + tig * 2;
            alv[2*j]   = alh[cw];   alv[2*j+1] = alh[cw+1];
            arv[2*j]   = arh[cw];   arv[2*j+1] = arh[cw+1];
        }
        float el1 = 0.f, er1 = 0.f, el2 = 0.f, er2 = 0.f;
#pragma unroll
        for (int j = 0; j < 8; j++) {
            el1 = fmaf(acc[j][0], alv[2*j], fmaf(acc[j][1], alv[2*j+1], el1));
            er1 = fmaf(acc[j][0], arv[2*j], fmaf(acc[j][1], arv[2*j+1], er1));
            el2 = fmaf(acc[j][2], alv[2*j], fmaf(acc[j][3], alv[2*j+1], el2));
            er2 = fmaf(acc[j][2], arv[2*j], fmaf(acc[j][3], arv[2*j+1], er2));
        }
#pragma unroll
        for (int o = 1; o <= 2; o <<= 1) {
            el1 += __shfl_xor_sync(0xffffffffu, el1, o);
            er1 += __shfl_xor_sync(0xffffffffu, er1, o);
            el2 += __shfl_xor_sync(0xffffffffu, el2, o);
            er2 += __shfl_xor_sync(0xffffffffu, er2, o);
        }
        if (tig == 0) {
            int r1 = bm + wm * 16 + grp;
            g_el[r1 * HH + hglob]       = el1;
            g_er[r1 * HH + hglob]       = er1;
            g_el[(r1 + 8) * HH + hglob] = el2;
            g_er[(r1 + 8) * HH + hglob] = er2;
        }
        float wmax = fmaxf(el1, el2);
#pragma unroll
        for (int o = 16; o >= 4; o >>= 1)
            wmax = fmaxf(wmax, __shfl_xor_sync(0xffffffffu, wmax, o));
        if (lane == 0) atomicMax(&elmaxU[hglob], fenc(wmax));
    }
}

// ---------------- per-node edge-softmax aggregation ----------------
// 2 nodes per warp; each half-warp (16 lanes) handles one node, lane owns 16 features.
__global__ __launch_bounds__(256) void agg_kernel(const __nv_bfloat16* __restrict__ zb,
                                                  const float* __restrict__ hprev,
                                                  float* __restrict__ hout,
                                                  const unsigned* __restrict__ elmaxU,
                                                  int residual, int emit_f16) {
    int gw   = (blockIdx.x * blockDim.x + threadIdx.x) >> 5;
    int lane = threadIdx.x & 31;
    int half = lane >> 4;
    int hl   = lane & 15;
    int n    = gw * 2 + half;
    if (n >= NN) return;
    unsigned hmask = 0xFFFFu << (half * 16);

    int base = g_rowptr[n];
    int deg  = g_rowptr[n + 1] - base;
    float4 er4 = ((const float4*)g_er)[n];
    uint4 Me = *(const uint4*)elmaxU;
    float m0 = lrelu(fdec(Me.x) + er4.x), m1 = lrelu(fdec(Me.y) + er4.y);
    float m2 = lrelu(fdec(Me.z) + er4.z), m3 = lrelu(fdec(Me.w) + er4.w);

    int hh = hl >> 2;    // lane owns features hl*16..hl*16+15 -> head = hl/4

    float acc[16];
#pragma unroll
    for (int i = 0; i < 16; i++) acc[i] = 0.f;
    float ssum = 0.f;

    for (int c = 0; c < deg; c += 16) {
        int rem = deg - c; if (rem > 16) rem = 16;
        int      s_l  = 0;
        unsigned wp01 = 0, wp23 = 0;
        if (hl < rem) {
            s_l = g_esrc[base + c + hl];
            float4 e4 = ((const float4*)g_el)[s_l];
            float wx = __expf(lrelu(e4.x + er4.x) - m0);
            float wy = __expf(lrelu(e4.y + er4.y) - m1);
            float wz = __expf(lrelu(e4.z + er4.z) - m2);
            float ww = __expf(lrelu(e4.w + er4.w) - m3);
            wp01 = h2_bits(__floats2half2_rn(wx, wy));
            wp23 = h2_bits(__floats2half2_rn(wz, ww));
        }
#pragma unroll 4
        for (int k = 0; k < rem; k++) {
            int      s  = __shfl_sync(hmask, s_l,  k, 16);
            unsigned a0 = __shfl_sync(hmask, wp01, k, 16);
            unsigned a1 = __shfl_sync(hmask, wp23, k, 16);
            unsigned wp = (hh < 2) ? a0 : a1;
            __half2  h2 = *reinterpret_cast<__half2*>(&wp);
            float w = (hh & 1) ? __high2float(h2) : __low2float(h2);
            ssum += w;
            const uint4* zr = (const uint4*)(zb + (size_t)s * HD + hl * 16);
            uint4 p0 = zr[0], p1 = zr[1];
            float f0, f1, f2, f3, f4, f5, f6, f7;
            bf2f(p0.x, f0, f1); bf2f(p0.y, f2, f3);
            bf2f(p0.z, f4, f5); bf2f(p0.w, f6, f7);
            acc[0] = fmaf(w, f0, acc[0]);  acc[1] = fmaf(w, f1, acc[1]);
            acc[2] = fmaf(w, f2, acc[2]);  acc[3] = fmaf(w, f3, acc[3]);
            acc[4] = fmaf(w, f4, acc[4]);  acc[5] = fmaf(w, f5, acc[5]);
            acc[6] = fmaf(w, f6, acc[6]);  acc[7] = fmaf(w, f7, acc[7]);
            bf2f(p1.x, f0, f1); bf2f(p1.y, f2, f3);
            bf2f(p1.z, f4, f5); bf2f(p1.w, f6, f7);
            acc[8]  = fmaf(w, f0, acc[8]);  acc[9]  = fmaf(w, f1, acc[9]);
            acc[10] = fmaf(w, f2, acc[10]); acc[11] = fmaf(w, f3, acc[11]);
            acc[12] = fmaf(w, f4, acc[12]); acc[13] = fmaf(w, f5, acc[13]);
            acc[14] = fmaf(w, f6, acc[14]); acc[15] = fmaf(w, f7, acc[15]);
        }
    }

    float inv = 1.f / ssum;
    float o16[16];
#pragma unroll
    for (int i = 0; i < 16; i++) o16[i] = acc[i] * inv;
    size_t ob = (size_t)n * HD + hl * 16;
    if (residual) {
        const float4* pp = (const float4*)(hprev + ob);
#pragma unroll
        for (int q = 0; q < 4; q++) {
            float4 p = pp[q];
            o16[4*q+0] = elu1(o16[4*q+0] + p.x);
            o16[4*q+1] = elu1(o16[4*q+1] + p.y);
            o16[4*q+2] = elu1(o16[4*q+2] + p.z);
            o16[4*q+3] = elu1(o16[4*q+3] + p.w);
        }
    }
#pragma unroll
    for (int i = 0; i < 16; i++) o16[i] = elu1(o16[i]);
#pragma unroll
    for (int q = 0; q < 4; q++) {
        float4 v = {o16[4*q], o16[4*q+1], o16[4*q+2], o16[4*q+3]};
        *(float4*)(hout + ob + 4*q) = v;
    }

    if (emit_f16) {   // next layer's GEMM A operand
        uint4 pk0, pk1;
        __half2 e;
        e = __floats2half2_rn(o16[0],  o16[1]);  pk0.x = h2_bits(e);
        e = __floats2half2_rn(o16[2],  o16[3]);  pk0.y = h2_bits(e);
        e = __floats2half2_rn(o16[4],  o16[5]);  pk0.z = h2_bits(e);
        e = __floats2half2_rn(o16[6],  o16[7]);  pk0.w = h2_bits(e);
        e = __floats2half2_rn(o16[8],  o16[9]);  pk1.x = h2_bits(e);
        e = __floats2half2_rn(o16[10], o16[11]); pk1.y = h2_bits(e);
        e = __floats2half2_rn(o16[12], o16[13]); pk1.z = h2_bits(e);
        e = __floats2half2_rn(o16[14], o16[15]); pk1.w = h2_bits(e);
        *(uint4*)(g_af16 + ob)     = pk0;
        *(uint4*)(g_af16 + ob + 8) = pk1;
    }
}

// ---------------- pooling + classifier ----------------
__global__ __launch_bounds__(256) void pool_kernel(const float* __restrict__ h,
                                                   const float* __restrict__ Wc,
                                                   const float* __restrict__ bc,
                                                   float* __restrict__ out) {
    __shared__ float hg[HD];
    int g = blockIdx.x;
    int t = threadIdx.x;
    float s = 0.f;
    const float* base = h + (size_t)g * NPG * HD + t;
    for (int i = 0; i < NPG; i++) s += base[(size_t)i * HD];
    hg[t] = elu1(s * (1.f / NPG));
    __syncthreads();
    if (t < CC) {
        float acc = bc[t];
        for (int f = 0; f < HD; f++) acc = fmaf(hg[f], Wc[f * CC + t], acc);
        out[g * CC + t] = acc;
    }
}

// ---------------- launch ----------------
extern "C" void kernel_launch(void* const* d_in, const int* in_sizes, int n_in,
                              void* d_out, int out_size) {
    const float* x   = (const float*)d_in[0];
    const int*   src = (const int*)  d_in[1];
    const int*   dst = (const int*)  d_in[2];
    const float* W0  = (const float*)d_in[4];
    const float* al0 = (const float*)d_in[5];
    const float* ar0 = (const float*)d_in[6];
    const float* W1  = (const float*)d_in[7];
    const float* al1 = (const float*)d_in[8];
    const float* ar1 = (const float*)d_in[9];
    const float* W2  = (const float*)d_in[10];
    const float* al2 = (const float*)d_in[11];
    const float* ar2 = (const float*)d_in[12];
    const float* Wc  = (const float*)d_in[13];
    const float* bc  = (const float*)d_in[14];
    float* out = (float*)d_out;

    float *hA, *hB;
    __nv_bfloat16 *zb;
    __half *af16, *bf16;
    unsigned* emx;
    cudaGetSymbolAddress((void**)&zb,   g_zb);
    cudaGetSymbolAddress((void**)&hA,   g_hA);
    cudaGetSymbolAddress((void**)&hB,   g_hB);
    cudaGetSymbolAddress((void**)&af16, g_af16);
    cudaGetSymbolAddress((void**)&bf16, g_bf16);
    cudaGetSymbolAddress((void**)&emx,  g_elmaxU);

    cudaFuncSetAttribute(gemm_mma_kernel,
                         cudaFuncAttributeMaxDynamicSharedMemorySize, SMEM_GEMM);

    // fork CSR build onto a side stream, overlapped with conv + layer-0 GEMM
    cudaStream_t s2;
    cudaStreamCreateWithFlags(&s2, cudaStreamNonBlocking);
    cudaEvent_t evFork, evJoin;
    cudaEventCreateWithFlags(&evFork, cudaEventDisableTiming);
    cudaEventCreateWithFlags(&evJoin, cudaEventDisableTiming);

    cudaEventRecord(evFork, 0);
    cudaStreamWaitEvent(s2, evFork, 0);
    zero_deg_kernel<<<(NN + 255) / 256, 256, 0, s2>>>();
    hist_kernel<<<(EE + 255) / 256, 256, 0, s2>>>(dst);
    scan_kernel<<<1, 512, 0, s2>>>();
    scatter_kernel<<<(EE + 255) / 256, 256, 0, s2>>>(src, dst);
    cudaEventRecord(evJoin, s2);

    // main stream: single conversion kernel (x + all W + elmax reset)
    int convN = NN * 128 / 4 + (128 + 512) * HD;
    conv_kernel<<<(convN + 255) / 256, 256>>>(x, W0, W1, W2);

    dim3 ggrid(NN / 64, 2);

    gemm_mma_kernel<<<ggrid, 256, SMEM_GEMM>>>(af16, bf16, zb,
                                               emx + 0, al0, ar0, 128);
    cudaStreamWaitEvent(0, evJoin, 0);   // CSR ready before first agg
    agg_kernel<<<NN / 16, 256>>>(zb, nullptr, hA, emx + 0, 0, 1);

    // layer 1
    gemm_mma_kernel<<<ggrid, 256, SMEM_GEMM>>>(af16, bf16 + HD * HD, zb,
                                               emx + 4, al1, ar1, 256);
    agg_kernel<<<NN / 16, 256>>>(zb, hA, hB, emx + 4, 1, 1);

    // layer 2
    gemm_mma_kernel<<<ggrid, 256, SMEM_GEMM>>>(af16, bf16 + 2 * HD * HD, zb,
                                               emx + 8, al2, ar2, 256);
    agg_kernel<<<NN / 16, 256>>>(zb, hB, hA, emx + 8, 1, 0);

    pool_kernel<<<GG, 256>>>(hA, Wc, bc, out);
}

// round 13
// speedup vs baseline: 1.6098x; 1.6098x over previous
#include <cuda_runtime.h>
#include <cuda_bf16.h>
#include <cuda_fp16.h>
#include <math.h>
#include <stdint.h>

#define NN 20480
#define EE 327680
#define GG 64
#define HD 256     // H*D
#define HH 4
#define DD 64
#define CC 10
#define NPG (NN/GG)

// ---------------- scratch (static device globals; no allocation) ----------------
__device__ __nv_bfloat16 g_zb[NN*HD];        // z in bf16 (agg gather operand)
__device__ float g_hA[NN*HD];
__device__ float g_hB[NN*HD];
__device__ float g_el[NN*HH];
__device__ float g_er[NN*HH];
__device__ unsigned g_elmaxU[3*HH];          // encoded per-head el max, per layer
__device__ int   g_deg[NN];
__device__ int   g_rowptr[NN+1];
__device__ int   g_cursor[NN];
__device__ int   g_esrc[EE];
__device__ __half g_af16[NN*HD];             // GEMM A operand (fp16)
__device__ __half g_bf16[3][HD*HD];          // W per layer: [K][256] fp16

__device__ __forceinline__ float lrelu(float x) { return x > 0.f ? x : 0.2f * x; }
__device__ __forceinline__ float elu1 (float x) { return x > 0.f ? x : expm1f(x); }

// monotone float<->uint encoding for atomicMax on floats
__device__ __forceinline__ unsigned fenc(float f) {
    unsigned u = __float_as_uint(f);
    return (u & 0x80000000u) ? ~u : (u | 0x80000000u);
}
__device__ __forceinline__ float fdec(unsigned u) {
    return (u & 0x80000000u) ? __uint_as_float(u & 0x7fffffffu) : __uint_as_float(~u);
}
__device__ __forceinline__ unsigned h2_bits(__half2 h) {
    return *reinterpret_cast<unsigned*>(&h);
}
// exact bf16 pair -> two f32 (2 inst)
__device__ __forceinline__ void bf2f(unsigned r, float& lo, float& hi) {
    lo = __uint_as_float(r << 16);
    hi = __uint_as_float(r & 0xffff0000u);
}

__device__ __forceinline__ uint32_t smem_u32(const void* p) {
    uint32_t a;
    asm("{ .reg .u64 t; cvta.to.shared.u64 t, %1; cvt.u32.u64 %0, t; }" : "=r"(a) : "l"(p));
    return a;
}
__device__ __forceinline__ void ldmat4(uint32_t* r, uint32_t a) {
    asm volatile("ldmatrix.sync.aligned.m8n8.x4.shared.b16 {%0,%1,%2,%3}, [%4];"
        : "=r"(r[0]), "=r"(r[1]), "=r"(r[2]), "=r"(r[3]) : "r"(a));
}
__device__ __forceinline__ void ldmat4t(uint32_t* r, uint32_t a) {
    asm volatile("ldmatrix.sync.aligned.m8n8.x4.trans.shared.b16 {%0,%1,%2,%3}, [%4];"
        : "=r"(r[0]), "=r"(r[1]), "=r"(r[2]), "=r"(r[3]) : "r"(a));
}
__device__ __forceinline__ void mma16816h(float* c, const uint32_t* a, const uint32_t* b) {
    asm volatile(
        "mma.sync.aligned.m16n8k16.row.col.f32.f16.f16.f32 "
        "{%0,%1,%2,%3}, {%4,%5,%6,%7}, {%8,%9}, {%0,%1,%2,%3};"
        : "+f"(c[0]), "+f"(c[1]), "+f"(c[2]), "+f"(c[3])
        : "r"(a[0]), "r"(a[1]), "r"(a[2]), "r"(a[3]), "r"(b[0]), "r"(b[1]));
}
#define CP16(s, g) asm volatile("cp.async.cg.shared.global [%0], [%1], 16;" \
    :: "r"(s), "l"(__cvta_generic_to_global(g)))
#define CP_COMMIT() asm volatile("cp.async.commit_group;" ::: "memory")
#define CP_WAIT0()  asm volatile("cp.async.wait_group 0;" ::: "memory")
#define CP_WAIT1()  asm volatile("cp.async.wait_group 1;" ::: "memory")

// ---------------- CSR build ----------------
__global__ void zero_deg_kernel() {
    int i = blockIdx.x * blockDim.x + threadIdx.x;
    if (i < NN) g_deg[i] = 0;
}
__global__ void hist_kernel(const int* __restrict__ dst) {
    int i = blockIdx.x * blockDim.x + threadIdx.x;
    if (i < EE) atomicAdd(&g_deg[dst[i]], 1);
}
__global__ void scan_kernel() {
    __shared__ int part[512];
    const int CH = NN / 512;
    int t = threadIdx.x;
    int s = 0;
    for (int i = 0; i < CH; i++) s += g_deg[t*CH + i];
    part[t] = s;
    __syncthreads();
    if (t == 0) {
        int r = 0;
        for (int i = 0; i < 512; i++) { int v = part[i]; part[i] = r; r += v; }
        g_rowptr[NN] = r;
    }
    __syncthreads();
    int run = part[t];
    for (int i = 0; i < CH; i++) {
        int idx = t*CH + i;
        g_rowptr[idx] = run;
        g_cursor[idx] = run;
        run += g_deg[idx];
    }
}
__global__ void scatter_kernel(const int* __restrict__ src, const int* __restrict__ dst) {
    int i = blockIdx.x * blockDim.x + threadIdx.x;
    if (i < EE) {
        int p = atomicAdd(&g_cursor[dst[i]], 1);
        g_esrc[p] = src[i];
    }
}

// ---------------- conversions: x -> fp16 A, W0..W2 -> fp16 B, elmax reset ----------------
__global__ void conv_kernel(const float* __restrict__ x,
                            const float* __restrict__ W0,
                            const float* __restrict__ W1,
                            const float* __restrict__ W2) {
    int i = blockIdx.x * blockDim.x + threadIdx.x;
    if (blockIdx.x == 0 && threadIdx.x < 3 * HH) g_elmaxU[threadIdx.x] = 0u;
    const int NX4 = NN * 128 / 4;   // x as float4
    if (i < NX4) {
        float4 v = ((const float4*)x)[i];
        ((__half2*)g_af16)[2*i]   = __floats2half2_rn(v.x, v.y);
        ((__half2*)g_af16)[2*i+1] = __floats2half2_rn(v.z, v.w);
        return;
    }
    int j = i - NX4;
    const float* B; int layer, off;
    if (j < 128 * HD)           { B = W0; layer = 0; off = j; }
    else if (j < (128+256)*HD)  { B = W1; layer = 1; off = j - 128 * HD; }
    else if (j < (128+512)*HD)  { B = W2; layer = 2; off = j - (128+256) * HD; }
    else return;
    g_bf16[layer][off] = __float2half(B[off]);
}

// ---------------- fp16 mma.sync GEMM + fused attn projections + fused el-max ----------------
// CTA 64(M)x128(N), 8 warps (warp = 16x64), K chunks of 32, cp.async double buffer.
#define ARB 80        // A smem row bytes (32 fp16 = 64B + pad)
#define BRB 272       // B smem row bytes (128 fp16 = 256B + pad)
#define S_B   5120    // 64 rows * ARB
#define BUF   13824   // S_B + 32*BRB
#define SMEM_GEMM (2*BUF)

__global__ __launch_bounds__(256, 3) void gemm_mma_kernel(
    const __half* __restrict__ A, const __half* __restrict__ B,
    __nv_bfloat16* __restrict__ Zb, unsigned* __restrict__ elmaxU,
    const float* __restrict__ al, const float* __restrict__ ar, int K) {
    extern __shared__ char sm[];
    uint32_t sb = smem_u32(sm);
    int tid = threadIdx.x, lane = tid & 31, wid = tid >> 5;
    int wm = wid & 3, wn = wid >> 2;
    int bm = blockIdx.x * 64, bn = blockIdx.y * 128;

    float acc[8][4];
#pragma unroll
    for (int j = 0; j < 8; j++)
#pragma unroll
        for (int q = 0; q < 4; q++) acc[j][q] = 0.f;

    auto issue = [&](int c, int buf) {
        int k0 = c * 32;
        uint32_t s0 = sb + buf * BUF;
        {
            int arow = tid >> 2, ach = tid & 3;
            const __half* ga = A + (size_t)(bm + arow) * K + k0 + ach * 8;
            CP16(s0 + arow * ARB + ach * 16, ga);
        }
#pragma unroll
        for (int r = 0; r < 2; r++) {
            int idx  = tid + r * 256;
            int brow = idx >> 4, bch = idx & 15;
            const __half* gb = B + (size_t)(k0 + brow) * HD + bn + bch * 8;
            CP16(s0 + S_B + brow * BRB + bch * 16, gb);
        }
    };

    auto compute = [&](int buf) {
        uint32_t s0 = sb + buf * BUF;
#pragma unroll
        for (int ks = 0; ks < 32; ks += 16) {
            uint32_t ah[4];
            {
                int row = wm * 16 + (lane & 15);
                uint32_t ad = s0 + row * ARB + (ks + (lane >> 4) * 8) * 2;
                ldmat4(ah, ad);
            }
#pragma unroll
            for (int jj = 0; jj < 4; jj++) {
                int krow = ks + (lane & 15);
                int ncol = wn * 64 + jj * 16 + (lane >> 4) * 8;
                uint32_t bd = s0 + S_B + krow * BRB + ncol * 2;
                uint32_t bh[4];
                ldmat4t(bh, bd);
                mma16816h(acc[2*jj],   ah, bh);
                mma16816h(acc[2*jj+1], ah, bh + 2);
            }
        }
    };

    int nch = K >> 5;
    issue(0, 0);
    CP_COMMIT();
    for (int c = 0; c < nch; c++) {
        if (c + 1 < nch) {
            issue(c + 1, (c + 1) & 1);
            CP_COMMIT();
            CP_WAIT1();
        } else {
            CP_WAIT0();
        }
        __syncthreads();
        compute(c & 1);
        __syncthreads();
    }

    int grp = lane >> 2, tig = lane & 3;

    // ---- store z as bf16 (rows bm+wm*16+grp and +8) ----
    {
        int rbase = bm + wm * 16 + grp;
#pragma unroll
        for (int j = 0; j < 8; j++) {
            int col = bn + wn * 64 + j * 8 + tig * 2;
            __nv_bfloat162 b0 = __floats2bfloat162_rn(acc[j][0], acc[j][1]);
            __nv_bfloat162 b1 = __floats2bfloat162_rn(acc[j][2], acc[j][3]);
            *(__nv_bfloat162*)(Zb + (size_t)rbase * HD + col)       = b0;
            *(__nv_bfloat162*)(Zb + (size_t)(rbase + 8) * HD + col) = b1;
        }
    }

    {   // ---- fused el/er for head hglob + global el-max atomic ----
        int hglob = (bn >> 6) + wn;
        const float* alh = al + hglob * DD;
        const float* arh = ar + hglob * DD;
        float alv[16], arv[16];
#pragma unroll
        for (int j = 0; j < 8; j++) {
            int cw = j * 8 + tig * 2;
            alv[2*j]   = alh[cw];   alv[2*j+1] = alh[cw+1];
            arv[2*j]   = arh[cw];   arv[2*j+1] = arh[cw+1];
        }
        float el1 = 0.f, er1 = 0.f, el2 = 0.f, er2 = 0.f;
#pragma unroll
        for (int j = 0; j < 8; j++) {
            el1 = fmaf(acc[j][0], alv[2*j], fmaf(acc[j][1], alv[2*j+1], el1));
            er1 = fmaf(acc[j][0], arv[2*j], fmaf(acc[j][1], arv[2*j+1], er1));
            el2 = fmaf(acc[j][2], alv[2*j], fmaf(acc[j][3], alv[2*j+1], el2));
            er2 = fmaf(acc[j][2], arv[2*j], fmaf(acc[j][3], arv[2*j+1], er2));
        }
#pragma unroll
        for (int o = 1; o <= 2; o <<= 1) {
            el1 += __shfl_xor_sync(0xffffffffu, el1, o);
            er1 += __shfl_xor_sync(0xffffffffu, er1, o);
            el2 += __shfl_xor_sync(0xffffffffu, el2, o);
            er2 += __shfl_xor_sync(0xffffffffu, er2, o);
        }
        if (tig == 0) {
            int r1 = bm + wm * 16 + grp;
            g_el[r1 * HH + hglob]       = el1;
            g_er[r1 * HH + hglob]       = er1;
            g_el[(r1 + 8) * HH + hglob] = el2;
            g_er[(r1 + 8) * HH + hglob] = er2;
        }
        float wmax = fmaxf(el1, el2);
#pragma unroll
        for (int o = 16; o >= 4; o >>= 1)
            wmax = fmaxf(wmax, __shfl_xor_sync(0xffffffffu, wmax, o));
        if (lane == 0) atomicMax(&elmaxU[hglob], fenc(wmax));
    }
}

// ---------------- per-node edge-softmax aggregation ----------------
// 2 nodes per warp; each half-warp (16 lanes) handles one node, lane owns 16 features.
__global__ __launch_bounds__(256) void agg_kernel(const __nv_bfloat16* __restrict__ zb,
                                                  const float* __restrict__ hprev,
                                                  float* __restrict__ hout,
                                                  const unsigned* __restrict__ elmaxU,
                                                  int residual, int emit_f16) {
    int gw   = (blockIdx.x * blockDim.x + threadIdx.x) >> 5;
    int lane = threadIdx.x & 31;
    int half = lane >> 4;
    int hl   = lane & 15;
    int n    = gw * 2 + half;
    if (n >= NN) return;
    unsigned hmask = 0xFFFFu << (half * 16);

    int base = g_rowptr[n];
    int deg  = g_rowptr[n + 1] - base;
    float4 er4 = ((const float4*)g_er)[n];
    uint4 Me = *(const uint4*)elmaxU;
    float m0 = lrelu(fdec(Me.x) + er4.x), m1 = lrelu(fdec(Me.y) + er4.y);
    float m2 = lrelu(fdec(Me.z) + er4.z), m3 = lrelu(fdec(Me.w) + er4.w);

    int hh = hl >> 2;    // lane owns features hl*16..hl*16+15 -> head = hl/4

    float acc[16];
#pragma unroll
    for (int i = 0; i < 16; i++) acc[i] = 0.f;
    float ssum = 0.f;

    for (int c = 0; c < deg; c += 16) {
        int rem = deg - c; if (rem > 16) rem = 16;
        int      s_l  = 0;
        unsigned wp01 = 0, wp23 = 0;
        if (hl < rem) {
            s_l = g_esrc[base + c + hl];
            float4 e4 = ((const float4*)g_el)[s_l];
            float wx = __expf(lrelu(e4.x + er4.x) - m0);
            float wy = __expf(lrelu(e4.y + er4.y) - m1);
            float wz = __expf(lrelu(e4.z + er4.z) - m2);
            float ww = __expf(lrelu(e4.w + er4.w) - m3);
            wp01 = h2_bits(__floats2half2_rn(wx, wy));
            wp23 = h2_bits(__floats2half2_rn(wz, ww));
        }
#pragma unroll 4
        for (int k = 0; k < rem; k++) {
            int      s  = __shfl_sync(hmask, s_l,  k, 16);
            unsigned a0 = __shfl_sync(hmask, wp01, k, 16);
            unsigned a1 = __shfl_sync(hmask, wp23, k, 16);
            unsigned wp = (hh < 2) ? a0 : a1;
            __half2  h2 = *reinterpret_cast<__half2*>(&wp);
            float w = (hh & 1) ? __high2float(h2) : __low2float(h2);
            ssum += w;
            const uint4* zr = (const uint4*)(zb + (size_t)s * HD + hl * 16);
            uint4 p0 = zr[0], p1 = zr[1];
            float f0, f1, f2, f3, f4, f5, f6, f7;
            bf2f(p0.x, f0, f1); bf2f(p0.y, f2, f3);
            bf2f(p0.z, f4, f5); bf2f(p0.w, f6, f7);
            acc[0] = fmaf(w, f0, acc[0]);  acc[1] = fmaf(w, f1, acc[1]);
            acc[2] = fmaf(w, f2, acc[2]);  acc[3] = fmaf(w, f3, acc[3]);
            acc[4] = fmaf(w, f4, acc[4]);  acc[5] = fmaf(w, f5, acc[5]);
            acc[6] = fmaf(w, f6, acc[6]);  acc[7] = fmaf(w, f7, acc[7]);
            bf2f(p1.x, f0, f1); bf2f(p1.y, f2, f3);
            bf2f(p1.z, f4, f5); bf2f(p1.w, f6, f7);
            acc[8]  = fmaf(w, f0, acc[8]);  acc[9]  = fmaf(w, f1, acc[9]);
            acc[10] = fmaf(w, f2, acc[10]); acc[11] = fmaf(w, f3, acc[11]);
            acc[12] = fmaf(w, f4, acc[12]); acc[13] = fmaf(w, f5, acc[13]);
            acc[14] = fmaf(w, f6, acc[14]); acc[15] = fmaf(w, f7, acc[15]);
        }
    }

    float inv = 1.f / ssum;
    float o16[16];
#pragma unroll
    for (int i = 0; i < 16; i++) o16[i] = acc[i] * inv;
    size_t ob = (size_t)n * HD + hl * 16;
    if (residual) {
        const float4* pp = (const float4*)(hprev + ob);
#pragma unroll
        for (int q = 0; q < 4; q++) {
            float4 p = pp[q];
            o16[4*q+0] = elu1(o16[4*q+0] + p.x);
            o16[4*q+1] = elu1(o16[4*q+1] + p.y);
            o16[4*q+2] = elu1(o16[4*q+2] + p.z);
            o16[4*q+3] = elu1(o16[4*q+3] + p.w);
        }
    }
#pragma unroll
    for (int i = 0; i < 16; i++) o16[i] = elu1(o16[i]);
#pragma unroll
    for (int q = 0; q < 4; q++) {
        float4 v = {o16[4*q], o16[4*q+1], o16[4*q+2], o16[4*q+3]};
        *(float4*)(hout + ob + 4*q) = v;
    }

    if (emit_f16) {   // next layer's GEMM A operand
        uint4 pk0, pk1;
        __half2 e;
        e = __floats2half2_rn(o16[0],  o16[1]);  pk0.x = h2_bits(e);
        e = __floats2half2_rn(o16[2],  o16[3]);  pk0.y = h2_bits(e);
        e = __floats2half2_rn(o16[4],  o16[5]);  pk0.z = h2_bits(e);
        e = __floats2half2_rn(o16[6],  o16[7]);  pk0.w = h2_bits(e);
        e = __floats2half2_rn(o16[8],  o16[9]);  pk1.x = h2_bits(e);
        e = __floats2half2_rn(o16[10], o16[11]); pk1.y = h2_bits(e);
        e = __floats2half2_rn(o16[12], o16[13]); pk1.z = h2_bits(e);
        e = __floats2half2_rn(o16[14], o16[15]); pk1.w = h2_bits(e);
        *(uint4*)(g_af16 + ob)     = pk0;
        *(uint4*)(g_af16 + ob + 8) = pk1;
    }
}

// ---------------- pooling + classifier ----------------
__global__ __launch_bounds__(256) void pool_kernel(const float* __restrict__ h,
                                                   const float* __restrict__ Wc,
                                                   const float* __restrict__ bc,
                                                   float* __restrict__ out) {
    __shared__ float hg[HD];
    int g = blockIdx.x;
    int t = threadIdx.x;
    float s = 0.f;
    const float* base = h + (size_t)g * NPG * HD + t;
    for (int i = 0; i < NPG; i++) s += base[(size_t)i * HD];
    hg[t] = elu1(s * (1.f / NPG));
    __syncthreads();
    if (t < CC) {
        float acc = bc[t];
        for (int f = 0; f < HD; f++) acc = fmaf(hg[f], Wc[f * CC + t], acc);
        out[g * CC + t] = acc;
    }
}

// ---------------- launch ----------------
extern "C" void kernel_launch(void* const* d_in, const int* in_sizes, int n_in,
                              void* d_out, int out_size) {
    const float* x   = (const float*)d_in[0];
    const int*   src = (const int*)  d_in[1];
    const int*   dst = (const int*)  d_in[2];
    const float* W0  = (const float*)d_in[4];
    const float* al0 = (const float*)d_in[5];
    const float* ar0 = (const float*)d_in[6];
    const float* W1  = (const float*)d_in[7];
    const float* al1 = (const float*)d_in[8];
    const float* ar1 = (const float*)d_in[9];
    const float* W2  = (const float*)d_in[10];
    const float* al2 = (const float*)d_in[11];
    const float* ar2 = (const float*)d_in[12];
    const float* Wc  = (const float*)d_in[13];
    const float* bc  = (const float*)d_in[14];
    float* out = (float*)d_out;

    float *hA, *hB;
    __nv_bfloat16 *zb;
    __half *af16, *bf16;
    unsigned* emx;
    cudaGetSymbolAddress((void**)&zb,   g_zb);
    cudaGetSymbolAddress((void**)&hA,   g_hA);
    cudaGetSymbolAddress((void**)&hB,   g_hB);
    cudaGetSymbolAddress((void**)&af16, g_af16);
    cudaGetSymbolAddress((void**)&bf16, g_bf16);
    cudaGetSymbolAddress((void**)&emx,  g_elmaxU);

    cudaFuncSetAttribute(gemm_mma_kernel,
                         cudaFuncAttributeMaxDynamicSharedMemorySize, SMEM_GEMM);

    // fork CSR build onto a side stream, overlapped with conv + layer-0 GEMM
    cudaStream_t s2;
    cudaStreamCreateWithFlags(&s2, cudaStreamNonBlocking);
    cudaEvent_t evFork, evJoin;
    cudaEventCreateWithFlags(&evFork, cudaEventDisableTiming);
    cudaEventCreateWithFlags(&evJoin, cudaEventDisableTiming);

    cudaEventRecord(evFork, 0);
    cudaStreamWaitEvent(s2, evFork, 0);
    zero_deg_kernel<<<(NN + 255) / 256, 256, 0, s2>>>();
    hist_kernel<<<(EE + 255) / 256, 256, 0, s2>>>(dst);
    scan_kernel<<<1, 512, 0, s2>>>();
    scatter_kernel<<<(EE + 255) / 256, 256, 0, s2>>>(src, dst);
    cudaEventRecord(evJoin, s2);

    // main stream: single conversion kernel (x + all W + elmax reset)
    int convN = NN * 128 / 4 + (128 + 512) * HD;
    conv_kernel<<<(convN + 255) / 256, 256>>>(x, W0, W1, W2);

    dim3 ggrid(NN / 64, 2);

    gemm_mma_kernel<<<ggrid, 256, SMEM_GEMM>>>(af16, bf16, zb,
                                               emx + 0, al0, ar0, 128);
    cudaStreamWaitEvent(0, evJoin, 0);   // CSR ready before first agg
    agg_kernel<<<NN / 16, 256>>>(zb, nullptr, hA, emx + 0, 0, 1);

    // layer 1
    gemm_mma_kernel<<<ggrid, 256, SMEM_GEMM>>>(af16, bf16 + HD * HD, zb,
                                               emx + 4, al1, ar1, 256);
    agg_kernel<<<NN / 16, 256>>>(zb, hA, hB, emx + 4, 1, 1);

    // layer 2
    gemm_mma_kernel<<<ggrid, 256, SMEM_GEMM>>>(af16, bf16 + 2 * HD * HD, zb,
                                               emx + 8, al2, ar2, 256);
    agg_kernel<<<NN / 16, 256>>>(zb, hB, hA, emx + 8, 1, 0);

    pool_kernel<<<GG, 256>>>(hA, Wc, bc, out);
}

// round 14
// speedup vs baseline: 1.7612x; 1.0940x over previous
#include <cuda_runtime.h>
#include <cuda_bf16.h>
#include <cuda_fp16.h>
#include <math.h>
#include <stdint.h>

#define NN 20480
#define EE 327680
#define GG 64
#define HD 256     // H*D
#define HH 4
#define DD 64
#define CC 10
#define NPG (NN/GG)

// ---------------- scratch (static device globals; no allocation) ----------------
__device__ __half g_zh[NN*HD];               // z in fp16 (agg gather operand)
__device__ float g_hA[NN*HD];
__device__ float g_hB[NN*HD];
__device__ float g_el[NN*HH];
__device__ float g_er[NN*HH];
__device__ unsigned g_elmaxU[3*HH];          // encoded per-head el max, per layer
__device__ int   g_deg[NN];
__device__ int   g_rowptr[NN+1];
__device__ int   g_cursor[NN];
__device__ int   g_esrc[EE];
__device__ __half g_af16[NN*HD];             // GEMM A operand (fp16)
__device__ __half g_bf16[3][HD*HD];          // W per layer: [K][256] fp16

__device__ __forceinline__ float lrelu(float x) { return x > 0.f ? x : 0.2f * x; }
__device__ __forceinline__ float elu1 (float x) { return x > 0.f ? x : expm1f(x); }

// monotone float<->uint encoding for atomicMax on floats
__device__ __forceinline__ unsigned fenc(float f) {
    unsigned u = __float_as_uint(f);
    return (u & 0x80000000u) ? ~u : (u | 0x80000000u);
}
__device__ __forceinline__ float fdec(unsigned u) {
    return (u & 0x80000000u) ? __uint_as_float(u & 0x7fffffffu) : __uint_as_float(~u);
}
__device__ __forceinline__ unsigned h2_bits(__half2 h) {
    return *reinterpret_cast<unsigned*>(&h);
}
__device__ __forceinline__ __half2 bits_h2(unsigned u) {
    return *reinterpret_cast<__half2*>(&u);
}

__device__ __forceinline__ uint32_t smem_u32(const void* p) {
    uint32_t a;
    asm("{ .reg .u64 t; cvta.to.shared.u64 t, %1; cvt.u32.u64 %0, t; }" : "=r"(a) : "l"(p));
    return a;
}
__device__ __forceinline__ void ldmat4(uint32_t* r, uint32_t a) {
    asm volatile("ldmatrix.sync.aligned.m8n8.x4.shared.b16 {%0,%1,%2,%3}, [%4];"
        : "=r"(r[0]), "=r"(r[1]), "=r"(r[2]), "=r"(r[3]) : "r"(a));
}
__device__ __forceinline__ void ldmat4t(uint32_t* r, uint32_t a) {
    asm volatile("ldmatrix.sync.aligned.m8n8.x4.trans.shared.b16 {%0,%1,%2,%3}, [%4];"
        : "=r"(r[0]), "=r"(r[1]), "=r"(r[2]), "=r"(r[3]) : "r"(a));
}
__device__ __forceinline__ void mma16816h(float* c, const uint32_t* a, const uint32_t* b) {
    asm volatile(
        "mma.sync.aligned.m16n8k16.row.col.f32.f16.f16.f32 "
        "{%0,%1,%2,%3}, {%4,%5,%6,%7}, {%8,%9}, {%0,%1,%2,%3};"
        : "+f"(c[0]), "+f"(c[1]), "+f"(c[2]), "+f"(c[3])
        : "r"(a[0]), "r"(a[1]), "r"(a[2]), "r"(a[3]), "r"(b[0]), "r"(b[1]));
}
#define CP16(s, g) asm volatile("cp.async.cg.shared.global [%0], [%1], 16;" \
    :: "r"(s), "l"(__cvta_generic_to_global(g)))
#define CP_COMMIT() asm volatile("cp.async.commit_group;" ::: "memory")
#define CP_WAIT0()  asm volatile("cp.async.wait_group 0;" ::: "memory")
#define CP_WAIT1()  asm volatile("cp.async.wait_group 1;" ::: "memory")

// ---------------- CSR build ----------------
__global__ void zero_deg_kernel() {
    int i = blockIdx.x * blockDim.x + threadIdx.x;
    if (i < NN) g_deg[i] = 0;
}
__global__ void hist_kernel(const int* __restrict__ dst) {
    int i = blockIdx.x * blockDim.x + threadIdx.x;
    if (i < EE) atomicAdd(&g_deg[dst[i]], 1);
}
__global__ void scan_kernel() {
    __shared__ int part[512];
    const int CH = NN / 512;
    int t = threadIdx.x;
    int s = 0;
    for (int i = 0; i < CH; i++) s += g_deg[t*CH + i];
    part[t] = s;
    __syncthreads();
    if (t == 0) {
        int r = 0;
        for (int i = 0; i < 512; i++) { int v = part[i]; part[i] = r; r += v; }
        g_rowptr[NN] = r;
    }
    __syncthreads();
    int run = part[t];
    for (int i = 0; i < CH; i++) {
        int idx = t*CH + i;
        g_rowptr[idx] = run;
        g_cursor[idx] = run;
        run += g_deg[idx];
    }
}
__global__ void scatter_kernel(const int* __restrict__ src, const int* __restrict__ dst) {
    int i = blockIdx.x * blockDim.x + threadIdx.x;
    if (i < EE) {
        int p = atomicAdd(&g_cursor[dst[i]], 1);
        g_esrc[p] = src[i];
    }
}

// ---------------- conversions: x -> fp16 A, W0..W2 -> fp16 B, elmax reset ----------------
__global__ void conv_kernel(const float* __restrict__ x,
                            const float* __restrict__ W0,
                            const float* __restrict__ W1,
                            const float* __restrict__ W2) {
    int i = blockIdx.x * blockDim.x + threadIdx.x;
    if (blockIdx.x == 0 && threadIdx.x < 3 * HH) g_elmaxU[threadIdx.x] = 0u;
    const int NX4 = NN * 128 / 4;   // x as float4
    if (i < NX4) {
        float4 v = ((const float4*)x)[i];
        ((__half2*)g_af16)[2*i]   = __floats2half2_rn(v.x, v.y);
        ((__half2*)g_af16)[2*i+1] = __floats2half2_rn(v.z, v.w);
        return;
    }
    int j = i - NX4;
    const float* B; int layer, off;
    if (j < 128 * HD)           { B = W0; layer = 0; off = j; }
    else if (j < (128+256)*HD)  { B = W1; layer = 1; off = j - 128 * HD; }
    else if (j < (128+512)*HD)  { B = W2; layer = 2; off = j - (128+256) * HD; }
    else return;
    g_bf16[layer][off] = __float2half(B[off]);
}

// ---------------- fp16 mma.sync GEMM + fused attn projections + fused el-max ----------------
// CTA 64(M)x128(N), 8 warps (warp = 16x64), K chunks of 32, cp.async double buffer.
#define ARB 80        // A smem row bytes (32 fp16 = 64B + pad)
#define BRB 272       // B smem row bytes (128 fp16 = 256B + pad)
#define S_B   5120    // 64 rows * ARB
#define BUF   13824   // S_B + 32*BRB
#define SMEM_GEMM (2*BUF)

__global__ __launch_bounds__(256, 3) void gemm_mma_kernel(
    const __half* __restrict__ A, const __half* __restrict__ B,
    __half* __restrict__ Zh, unsigned* __restrict__ elmaxU,
    const float* __restrict__ al, const float* __restrict__ ar, int K) {
    extern __shared__ char sm[];
    uint32_t sb = smem_u32(sm);
    int tid = threadIdx.x, lane = tid & 31, wid = tid >> 5;
    int wm = wid & 3, wn = wid >> 2;
    int bm = blockIdx.x * 64, bn = blockIdx.y * 128;

    float acc[8][4];
#pragma unroll
    for (int j = 0; j < 8; j++)
#pragma unroll
        for (int q = 0; q < 4; q++) acc[j][q] = 0.f;

    auto issue = [&](int c, int buf) {
        int k0 = c * 32;
        uint32_t s0 = sb + buf * BUF;
        {
            int arow = tid >> 2, ach = tid & 3;
            const __half* ga = A + (size_t)(bm + arow) * K + k0 + ach * 8;
            CP16(s0 + arow * ARB + ach * 16, ga);
        }
#pragma unroll
        for (int r = 0; r < 2; r++) {
            int idx  = tid + r * 256;
            int brow = idx >> 4, bch = idx & 15;
            const __half* gb = B + (size_t)(k0 + brow) * HD + bn + bch * 8;
            CP16(s0 + S_B + brow * BRB + bch * 16, gb);
        }
    };

    auto compute = [&](int buf) {
        uint32_t s0 = sb + buf * BUF;
#pragma unroll
        for (int ks = 0; ks < 32; ks += 16) {
            uint32_t ah[4];
            {
                int row = wm * 16 + (lane & 15);
                uint32_t ad = s0 + row * ARB + (ks + (lane >> 4) * 8) * 2;
                ldmat4(ah, ad);
            }
#pragma unroll
            for (int jj = 0; jj < 4; jj++) {
                int krow = ks + (lane & 15);
                int ncol = wn * 64 + jj * 16 + (lane >> 4) * 8;
                uint32_t bd = s0 + S_B + krow * BRB + ncol * 2;
                uint32_t bh[4];
                ldmat4t(bh, bd);
                mma16816h(acc[2*jj],   ah, bh);
                mma16816h(acc[2*jj+1], ah, bh + 2);
            }
        }
    };

    int nch = K >> 5;
    issue(0, 0);
    CP_COMMIT();
    for (int c = 0; c < nch; c++) {
        if (c + 1 < nch) {
            issue(c + 1, (c + 1) & 1);
            CP_COMMIT();
            CP_WAIT1();
        } else {
            CP_WAIT0();
        }
        __syncthreads();
        compute(c & 1);
        __syncthreads();
    }

    int grp = lane >> 2, tig = lane & 3;

    // ---- store z as fp16 (rows bm+wm*16+grp and +8) ----
    {
        int rbase = bm + wm * 16 + grp;
#pragma unroll
        for (int j = 0; j < 8; j++) {
            int col = bn + wn * 64 + j * 8 + tig * 2;
            __half2 h0 = __floats2half2_rn(acc[j][0], acc[j][1]);
            __half2 h1 = __floats2half2_rn(acc[j][2], acc[j][3]);
            *(__half2*)(Zh + (size_t)rbase * HD + col)       = h0;
            *(__half2*)(Zh + (size_t)(rbase + 8) * HD + col) = h1;
        }
    }

    {   // ---- fused el/er for head hglob + global el-max atomic ----
        int hglob = (bn >> 6) + wn;
        const float* alh = al + hglob * DD;
        const float* arh = ar + hglob * DD;
        float alv[16], arv[16];
#pragma unroll
        for (int j = 0; j < 8; j++) {
            int cw = j * 8 + tig * 2;
            alv[2*j]   = alh[cw];   alv[2*j+1] = alh[cw+1];
            arv[2*j]   = arh[cw];   arv[2*j+1] = arh[cw+1];
        }
        float el1 = 0.f, er1 = 0.f, el2 = 0.f, er2 = 0.f;
#pragma unroll
        for (int j = 0; j < 8; j++) {
            el1 = fmaf(acc[j][0], alv[2*j], fmaf(acc[j][1], alv[2*j+1], el1));
            er1 = fmaf(acc[j][0], arv[2*j], fmaf(acc[j][1], arv[2*j+1], er1));
            el2 = fmaf(acc[j][2], alv[2*j], fmaf(acc[j][3], alv[2*j+1], el2));
            er2 = fmaf(acc[j][2], arv[2*j], fmaf(acc[j][3], arv[2*j+1], er2));
        }
#pragma unroll
        for (int o = 1; o <= 2; o <<= 1) {
            el1 += __shfl_xor_sync(0xffffffffu, el1, o);
            er1 += __shfl_xor_sync(0xffffffffu, er1, o);
            el2 += __shfl_xor_sync(0xffffffffu, el2, o);
            er2 += __shfl_xor_sync(0xffffffffu, er2, o);
        }
        if (tig == 0) {
            int r1 = bm + wm * 16 + grp;
            g_el[r1 * HH + hglob]       = el1;
            g_er[r1 * HH + hglob]       = er1;
            g_el[(r1 + 8) * HH + hglob] = el2;
            g_er[(r1 + 8) * HH + hglob] = er2;
        }
        float wmax = fmaxf(el1, el2);
#pragma unroll
        for (int o = 16; o >= 4; o >>= 1)
            wmax = fmaxf(wmax, __shfl_xor_sync(0xffffffffu, wmax, o));
        if (lane == 0) atomicMax(&elmaxU[hglob], fenc(wmax));
    }
}

// ---------------- per-node edge-softmax aggregation ----------------
// 2 nodes per warp; each half-warp (16 lanes) handles one node, lane owns 16 features.
// fp16 z gather + packed half2 accumulation (HFMA2); ssum kept in fp32.
__global__ __launch_bounds__(256) void agg_kernel(const __half* __restrict__ zh,
                                                  const float* __restrict__ hprev,
                                                  float* __restrict__ hout,
                                                  const unsigned* __restrict__ elmaxU,
                                                  int residual, int emit_f16) {
    int gw   = (blockIdx.x * blockDim.x + threadIdx.x) >> 5;
    int lane = threadIdx.x & 31;
    int half = lane >> 4;
    int hl   = lane & 15;
    int n    = gw * 2 + half;
    if (n >= NN) return;
    unsigned hmask = 0xFFFFu << (half * 16);

    int base = g_rowptr[n];
    int deg  = g_rowptr[n + 1] - base;
    float4 er4 = ((const float4*)g_er)[n];
    uint4 Me = *(const uint4*)elmaxU;
    float m0 = lrelu(fdec(Me.x) + er4.x), m1 = lrelu(fdec(Me.y) + er4.y);
    float m2 = lrelu(fdec(Me.z) + er4.z), m3 = lrelu(fdec(Me.w) + er4.w);

    int hh = hl >> 2;    // lane owns features hl*16..hl*16+15 -> head = hl/4
    unsigned psel = (hh & 1) ? 0x3232u : 0x1010u;   // duplicate hi or lo half

    __half2 acc2[8];
#pragma unroll
    for (int i = 0; i < 8; i++) acc2[i] = __float2half2_rn(0.f);
    float ssum = 0.f;

    for (int c = 0; c < deg; c += 16) {
        int rem = deg - c; if (rem > 16) rem = 16;
        int      s_l  = 0;
        unsigned wp01 = 0, wp23 = 0;
        if (hl < rem) {
            s_l = g_esrc[base + c + hl];
            float4 e4 = ((const float4*)g_el)[s_l];
            float wx = __expf(lrelu(e4.x + er4.x) - m0);
            float wy = __expf(lrelu(e4.y + er4.y) - m1);
            float wz = __expf(lrelu(e4.z + er4.z) - m2);
            float ww = __expf(lrelu(e4.w + er4.w) - m3);
            wp01 = h2_bits(__floats2half2_rn(wx, wy));
            wp23 = h2_bits(__floats2half2_rn(wz, ww));
        }
#pragma unroll 4
        for (int k = 0; k < rem; k++) {
            int      s  = __shfl_sync(hmask, s_l,  k, 16);
            unsigned a0 = __shfl_sync(hmask, wp01, k, 16);
            unsigned a1 = __shfl_sync(hmask, wp23, k, 16);
            unsigned wp = (hh < 2) ? a0 : a1;
            unsigned w2b = __byte_perm(wp, wp, psel);
            __half2  w2 = bits_h2(w2b);
            ssum += __low2float(w2);
            const uint4* zr = (const uint4*)(zh + (size_t)s * HD + hl * 16);
            uint4 p0 = zr[0], p1 = zr[1];
            acc2[0] = __hfma2(w2, bits_h2(p0.x), acc2[0]);
            acc2[1] = __hfma2(w2, bits_h2(p0.y), acc2[1]);
            acc2[2] = __hfma2(w2, bits_h2(p0.z), acc2[2]);
            acc2[3] = __hfma2(w2, bits_h2(p0.w), acc2[3]);
            acc2[4] = __hfma2(w2, bits_h2(p1.x), acc2[4]);
            acc2[5] = __hfma2(w2, bits_h2(p1.y), acc2[5]);
            acc2[6] = __hfma2(w2, bits_h2(p1.z), acc2[6]);
            acc2[7] = __hfma2(w2, bits_h2(p1.w), acc2[7]);
        }
    }

    float inv = 1.f / ssum;
    float o16[16];
#pragma unroll
    for (int i = 0; i < 8; i++) {
        float2 f = __half22float2(acc2[i]);
        o16[2*i]   = f.x * inv;
        o16[2*i+1] = f.y * inv;
    }
    size_t ob = (size_t)n * HD + hl * 16;
    if (residual) {
        const float4* pp = (const float4*)(hprev + ob);
#pragma unroll
        for (int q = 0; q < 4; q++) {
            float4 p = pp[q];
            o16[4*q+0] = elu1(o16[4*q+0] + p.x);
            o16[4*q+1] = elu1(o16[4*q+1] + p.y);
            o16[4*q+2] = elu1(o16[4*q+2] + p.z);
            o16[4*q+3] = elu1(o16[4*q+3] + p.w);
        }
    }
#pragma unroll
    for (int i = 0; i < 16; i++) o16[i] = elu1(o16[i]);
#pragma unroll
    for (int q = 0; q < 4; q++) {
        float4 v = {o16[4*q], o16[4*q+1], o16[4*q+2], o16[4*q+3]};
        *(float4*)(hout + ob + 4*q) = v;
    }

    if (emit_f16) {   // next layer's GEMM A operand
        uint4 pk0, pk1;
        __half2 e;
        e = __floats2half2_rn(o16[0],  o16[1]);  pk0.x = h2_bits(e);
        e = __floats2half2_rn(o16[2],  o16[3]);  pk0.y = h2_bits(e);
        e = __floats2half2_rn(o16[4],  o16[5]);  pk0.z = h2_bits(e);
        e = __floats2half2_rn(o16[6],  o16[7]);  pk0.w = h2_bits(e);
        e = __floats2half2_rn(o16[8],  o16[9]);  pk1.x = h2_bits(e);
        e = __floats2half2_rn(o16[10], o16[11]); pk1.y = h2_bits(e);
        e = __floats2half2_rn(o16[12], o16[13]); pk1.z = h2_bits(e);
        e = __floats2half2_rn(o16[14], o16[15]); pk1.w = h2_bits(e);
        *(uint4*)(g_af16 + ob)     = pk0;
        *(uint4*)(g_af16 + ob + 8) = pk1;
    }
}

// ---------------- pooling + classifier ----------------
__global__ __launch_bounds__(256) void pool_kernel(const float* __restrict__ h,
                                                   const float* __restrict__ Wc,
                                                   const float* __restrict__ bc,
                                                   float* __restrict__ out) {
    __shared__ float hg[HD];
    int g = blockIdx.x;
    int t = threadIdx.x;
    float s = 0.f;
    const float* base = h + (size_t)g * NPG * HD + t;
    for (int i = 0; i < NPG; i++) s += base[(size_t)i * HD];
    hg[t] = elu1(s * (1.f / NPG));
    __syncthreads();
    if (t < CC) {
        float acc = bc[t];
        for (int f = 0; f < HD; f++) acc = fmaf(hg[f], Wc[f * CC + t], acc);
        out[g * CC + t] = acc;
    }
}

// ---------------- launch ----------------
extern "C" void kernel_launch(void* const* d_in, const int* in_sizes, int n_in,
                              void* d_out, int out_size) {
    const float* x   = (const float*)d_in[0];
    const int*   src = (const int*)  d_in[1];
    const int*   dst = (const int*)  d_in[2];
    const float* W0  = (const float*)d_in[4];
    const float* al0 = (const float*)d_in[5];
    const float* ar0 = (const float*)d_in[6];
    const float* W1  = (const float*)d_in[7];
    const float* al1 = (const float*)d_in[8];
    const float* ar1 = (const float*)d_in[9];
    const float* W2  = (const float*)d_in[10];
    const float* al2 = (const float*)d_in[11];
    const float* ar2 = (const float*)d_in[12];
    const float* Wc  = (const float*)d_in[13];
    const float* bc  = (const float*)d_in[14];
    float* out = (float*)d_out;

    float *hA, *hB;
    __half *zh, *af16, *bf16;
    unsigned* emx;
    cudaGetSymbolAddress((void**)&zh,   g_zh);
    cudaGetSymbolAddress((void**)&hA,   g_hA);
    cudaGetSymbolAddress((void**)&hB,   g_hB);
    cudaGetSymbolAddress((void**)&af16, g_af16);
    cudaGetSymbolAddress((void**)&bf16, g_bf16);
    cudaGetSymbolAddress((void**)&emx,  g_elmaxU);

    cudaFuncSetAttribute(gemm_mma_kernel,
                         cudaFuncAttributeMaxDynamicSharedMemorySize, SMEM_GEMM);

    // fork CSR build onto a side stream, overlapped with conv + layer-0 GEMM
    cudaStream_t s2;
    cudaStreamCreateWithFlags(&s2, cudaStreamNonBlocking);
    cudaEvent_t evFork, evJoin;
    cudaEventCreateWithFlags(&evFork, cudaEventDisableTiming);
    cudaEventCreateWithFlags(&evJoin, cudaEventDisableTiming);

    cudaEventRecord(evFork, 0);
    cudaStreamWaitEvent(s2, evFork, 0);
    zero_deg_kernel<<<(NN + 255) / 256, 256, 0, s2>>>();
    hist_kernel<<<(EE + 255) / 256, 256, 0, s2>>>(dst);
    scan_kernel<<<1, 512, 0, s2>>>();
    scatter_kernel<<<(EE + 255) / 256, 256, 0, s2>>>(src, dst);
    cudaEventRecord(evJoin, s2);

    // main stream: single conversion kernel (x + all W + elmax reset)
    int convN = NN * 128 / 4 + (128 + 512) * HD;
    conv_kernel<<<(convN + 255) / 256, 256>>>(x, W0, W1, W2);

    dim3 ggrid(NN / 64, 2);

    gemm_mma_kernel<<<ggrid, 256, SMEM_GEMM>>>(af16, bf16, zh,
                                               emx + 0, al0, ar0, 128);
    cudaStreamWaitEvent(0, evJoin, 0);   // CSR ready before first agg
    agg_kernel<<<NN / 16, 256>>>(zh, nullptr, hA, emx + 0, 0, 1);

    // layer 1
    gemm_mma_kernel<<<ggrid, 256, SMEM_GEMM>>>(af16, bf16 + HD * HD, zh,
                                               emx + 4, al1, ar1, 256);
    agg_kernel<<<NN / 16, 256>>>(zh, hA, hB, emx + 4, 1, 1);

    // layer 2
    gemm_mma_kernel<<<ggrid, 256, SMEM_GEMM>>>(af16, bf16 + 2 * HD * HD, zh,
                                               emx + 8, al2, ar2, 256);
    agg_kernel<<<NN / 16, 256>>>(zh, hB, hA, emx + 8, 1, 0);

    pool_kernel<<<GG, 256>>>(hA, Wc, bc, out);
}

// round 15
// speedup vs baseline: 1.8417x; 1.0457x over previous
#include <cuda_runtime.h>
#include <cuda_bf16.h>
#include <cuda_fp16.h>
#include <math.h>
#include <stdint.h>

#define NN 20480
#define EE 327680
#define GG 64
#define HD 256     // H*D
#define HH 4
#define DD 64
#define CC 10
#define NPG (NN/GG)

// ---------------- scratch (static device globals; no allocation) ----------------
__device__ __half g_zh[NN*HD];               // z in fp16 (agg gather operand)
__device__ __half g_h16[2][NN*HD];           // activation ping-pong (fp16): GEMM A, residual, pool
__device__ float g_el[NN*HH];
__device__ float g_er[NN*HH];
__device__ unsigned g_elmaxU[3*HH];          // encoded per-head el max, per layer
__device__ int   g_deg[NN];
__device__ int   g_rowptr[NN+1];
__device__ int   g_cursor[NN];
__device__ int   g_esrc[EE];
__device__ __half g_bf16[3][HD*HD];          // W per layer: [K][256] fp16

__device__ __forceinline__ float lrelu(float x) { return x > 0.f ? x : 0.2f * x; }
__device__ __forceinline__ float elu1 (float x) { return x > 0.f ? x : expm1f(x); }

// monotone float<->uint encoding for atomicMax on floats
__device__ __forceinline__ unsigned fenc(float f) {
    unsigned u = __float_as_uint(f);
    return (u & 0x80000000u) ? ~u : (u | 0x80000000u);
}
__device__ __forceinline__ float fdec(unsigned u) {
    return (u & 0x80000000u) ? __uint_as_float(u & 0x7fffffffu) : __uint_as_float(~u);
}
__device__ __forceinline__ unsigned h2_bits(__half2 h) {
    return *reinterpret_cast<unsigned*>(&h);
}
__device__ __forceinline__ __half2 bits_h2(unsigned u) {
    return *reinterpret_cast<__half2*>(&u);
}

__device__ __forceinline__ uint32_t smem_u32(const void* p) {
    uint32_t a;
    asm("{ .reg .u64 t; cvta.to.shared.u64 t, %1; cvt.u32.u64 %0, t; }" : "=r"(a) : "l"(p));
    return a;
}
__device__ __forceinline__ void ldmat4(uint32_t* r, uint32_t a) {
    asm volatile("ldmatrix.sync.aligned.m8n8.x4.shared.b16 {%0,%1,%2,%3}, [%4];"
        : "=r"(r[0]), "=r"(r[1]), "=r"(r[2]), "=r"(r[3]) : "r"(a));
}
__device__ __forceinline__ void ldmat4t(uint32_t* r, uint32_t a) {
    asm volatile("ldmatrix.sync.aligned.m8n8.x4.trans.shared.b16 {%0,%1,%2,%3}, [%4];"
        : "=r"(r[0]), "=r"(r[1]), "=r"(r[2]), "=r"(r[3]) : "r"(a));
}
__device__ __forceinline__ void mma16816h(float* c, const uint32_t* a, const uint32_t* b) {
    asm volatile(
        "mma.sync.aligned.m16n8k16.row.col.f32.f16.f16.f32 "
        "{%0,%1,%2,%3}, {%4,%5,%6,%7}, {%8,%9}, {%0,%1,%2,%3};"
        : "+f"(c[0]), "+f"(c[1]), "+f"(c[2]), "+f"(c[3])
        : "r"(a[0]), "r"(a[1]), "r"(a[2]), "r"(a[3]), "r"(b[0]), "r"(b[1]));
}
#define CP16(s, g) asm volatile("cp.async.cg.shared.global [%0], [%1], 16;" \
    :: "r"(s), "l"(__cvta_generic_to_global(g)))
#define CP_COMMIT() asm volatile("cp.async.commit_group;" ::: "memory")
#define CP_WAIT0()  asm volatile("cp.async.wait_group 0;" ::: "memory")
#define CP_WAIT1()  asm volatile("cp.async.wait_group 1;" ::: "memory")

// ---------------- CSR build ----------------
__global__ void zero_deg_kernel() {
    int i = blockIdx.x * blockDim.x + threadIdx.x;
    if (i < NN) g_deg[i] = 0;
}
__global__ void hist_kernel(const int* __restrict__ dst) {
    int i = blockIdx.x * blockDim.x + threadIdx.x;
    if (i < EE) atomicAdd(&g_deg[dst[i]], 1);
}
__global__ void scan_kernel() {
    __shared__ int part[512];
    const int CH = NN / 512;
    int t = threadIdx.x;
    int s = 0;
    for (int i = 0; i < CH; i++) s += g_deg[t*CH + i];
    part[t] = s;
    __syncthreads();
    if (t == 0) {
        int r = 0;
        for (int i = 0; i < 512; i++) { int v = part[i]; part[i] = r; r += v; }
        g_rowptr[NN] = r;
    }
    __syncthreads();
    int run = part[t];
    for (int i = 0; i < CH; i++) {
        int idx = t*CH + i;
        g_rowptr[idx] = run;
        g_cursor[idx] = run;
        run += g_deg[idx];
    }
}
__global__ void scatter_kernel(const int* __restrict__ src, const int* __restrict__ dst) {
    int i = blockIdx.x * blockDim.x + threadIdx.x;
    if (i < EE) {
        int p = atomicAdd(&g_cursor[dst[i]], 1);
        g_esrc[p] = src[i];
    }
}

// ---------------- conversions: x -> fp16 (ping buffer 0), W0..W2 -> fp16, elmax reset ----------------
__global__ void conv_kernel(const float* __restrict__ x,
                            const float* __restrict__ W0,
                            const float* __restrict__ W1,
                            const float* __restrict__ W2) {
    int i = blockIdx.x * blockDim.x + threadIdx.x;
    if (blockIdx.x == 0 && threadIdx.x < 3 * HH) g_elmaxU[threadIdx.x] = 0u;
    const int NX4 = NN * 128 / 4;   // x as float4
    if (i < NX4) {
        float4 v = ((const float4*)x)[i];
        ((__half2*)g_h16[0])[2*i]   = __floats2half2_rn(v.x, v.y);
        ((__half2*)g_h16[0])[2*i+1] = __floats2half2_rn(v.z, v.w);
        return;
    }
    int j = i - NX4;
    const float* B; int layer, off;
    if (j < 128 * HD)           { B = W0; layer = 0; off = j; }
    else if (j < (128+256)*HD)  { B = W1; layer = 1; off = j - 128 * HD; }
    else if (j < (128+512)*HD)  { B = W2; layer = 2; off = j - (128+256) * HD; }
    else return;
    g_bf16[layer][off] = __float2half(B[off]);
}

// ---------------- fp16 mma.sync GEMM + fused attn projections + fused el-max ----------------
// CTA 64(M)x128(N), 8 warps (warp = 16x64), K chunks of 32, cp.async double buffer.
#define ARB 80        // A smem row bytes (32 fp16 = 64B + pad)
#define BRB 272       // B smem row bytes (128 fp16 = 256B + pad)
#define S_B   5120    // 64 rows * ARB
#define BUF   13824   // S_B + 32*BRB
#define SMEM_GEMM (2*BUF)

__global__ __launch_bounds__(256, 3) void gemm_mma_kernel(
    const __half* __restrict__ A, const __half* __restrict__ B,
    __half* __restrict__ Zh, unsigned* __restrict__ elmaxU,
    const float* __restrict__ al, const float* __restrict__ ar, int K) {
    extern __shared__ char sm[];
    uint32_t sb = smem_u32(sm);
    int tid = threadIdx.x, lane = tid & 31, wid = tid >> 5;
    int wm = wid & 3, wn = wid >> 2;
    int bm = blockIdx.x * 64, bn = blockIdx.y * 128;

    float acc[8][4];
#pragma unroll
    for (int j = 0; j < 8; j++)
#pragma unroll
        for (int q = 0; q < 4; q++) acc[j][q] = 0.f;

    auto issue = [&](int c, int buf) {
        int k0 = c * 32;
        uint32_t s0 = sb + buf * BUF;
        {
            int arow = tid >> 2, ach = tid & 3;
            const __half* ga = A + (size_t)(bm + arow) * K + k0 + ach * 8;
            CP16(s0 + arow * ARB + ach * 16, ga);
        }
#pragma unroll
        for (int r = 0; r < 2; r++) {
            int idx  = tid + r * 256;
            int brow = idx >> 4, bch = idx & 15;
            const __half* gb = B + (size_t)(k0 + brow) * HD + bn + bch * 8;
            CP16(s0 + S_B + brow * BRB + bch * 16, gb);
        }
    };

    auto compute = [&](int buf) {
        uint32_t s0 = sb + buf * BUF;
#pragma unroll
        for (int ks = 0; ks < 32; ks += 16) {
            uint32_t ah[4];
            {
                int row = wm * 16 + (lane & 15);
                uint32_t ad = s0 + row * ARB + (ks + (lane >> 4) * 8) * 2;
                ldmat4(ah, ad);
            }
#pragma unroll
            for (int jj = 0; jj < 4; jj++) {
                int krow = ks + (lane & 15);
                int ncol = wn * 64 + jj * 16 + (lane >> 4) * 8;
                uint32_t bd = s0 + S_B + krow * BRB + ncol * 2;
                uint32_t bh[4];
                ldmat4t(bh, bd);
                mma16816h(acc[2*jj],   ah, bh);
                mma16816h(acc[2*jj+1], ah, bh + 2);
            }
        }
    };

    int nch = K >> 5;
    issue(0, 0);
    CP_COMMIT();
    for (int c = 0; c < nch; c++) {
        if (c + 1 < nch) {
            issue(c + 1, (c + 1) & 1);
            CP_COMMIT();
            CP_WAIT1();
        } else {
            CP_WAIT0();
        }
        __syncthreads();
        compute(c & 1);
        __syncthreads();
    }

    int grp = lane >> 2, tig = lane & 3;

    // ---- store z as fp16 (rows bm+wm*16+grp and +8) ----
    {
        int rbase = bm + wm * 16 + grp;
#pragma unroll
        for (int j = 0; j < 8; j++) {
            int col = bn + wn * 64 + j * 8 + tig * 2;
            __half2 h0 = __floats2half2_rn(acc[j][0], acc[j][1]);
            __half2 h1 = __floats2half2_rn(acc[j][2], acc[j][3]);
            *(__half2*)(Zh + (size_t)rbase * HD + col)       = h0;
            *(__half2*)(Zh + (size_t)(rbase + 8) * HD + col) = h1;
        }
    }

    {   // ---- fused el/er for head hglob + global el-max atomic ----
        int hglob = (bn >> 6) + wn;
        const float* alh = al + hglob * DD;
        const float* arh = ar + hglob * DD;
        float alv[16], arv[16];
#pragma unroll
        for (int j = 0; j < 8; j++) {
            int cw = j * 8 + tig * 2;
            alv[2*j]   = alh[cw];   alv[2*j+1] = alh[cw+1];
            arv[2*j]   = arh[cw];   arv[2*j+1] = arh[cw+1];
        }
        float el1 = 0.f, er1 = 0.f, el2 = 0.f, er2 = 0.f;
#pragma unroll
        for (int j = 0; j < 8; j++) {
            el1 = fmaf(acc[j][0], alv[2*j], fmaf(acc[j][1], alv[2*j+1], el1));
            er1 = fmaf(acc[j][0], arv[2*j], fmaf(acc[j][1], arv[2*j+1], er1));
            el2 = fmaf(acc[j][2], alv[2*j], fmaf(acc[j][3], alv[2*j+1], el2));
            er2 = fmaf(acc[j][2], arv[2*j], fmaf(acc[j][3], arv[2*j+1], er2));
        }
#pragma unroll
        for (int o = 1; o <= 2; o <<= 1) {
            el1 += __shfl_xor_sync(0xffffffffu, el1, o);
            er1 += __shfl_xor_sync(0xffffffffu, er1, o);
            el2 += __shfl_xor_sync(0xffffffffu, el2, o);
            er2 += __shfl_xor_sync(0xffffffffu, er2, o);
        }
        if (tig == 0) {
            int r1 = bm + wm * 16 + grp;
            g_el[r1 * HH + hglob]       = el1;
            g_er[r1 * HH + hglob]       = er1;
            g_el[(r1 + 8) * HH + hglob] = el2;
            g_er[(r1 + 8) * HH + hglob] = er2;
        }
        float wmax = fmaxf(el1, el2);
#pragma unroll
        for (int o = 16; o >= 4; o >>= 1)
            wmax = fmaxf(wmax, __shfl_xor_sync(0xffffffffu, wmax, o));
        if (lane == 0) atomicMax(&elmaxU[hglob], fenc(wmax));
    }
}

// ---------------- per-node edge-softmax aggregation ----------------
// 2 nodes per warp; each half-warp (16 lanes) handles one node, lane owns 16 features.
// fp16 z gather + packed half2 accumulation (HFMA2); ssum in fp32.
// Output written ONCE as fp16 (feeds next GEMM, residual, and pool).
__global__ __launch_bounds__(256) void agg_kernel(const __half* __restrict__ zh,
                                                  const __half* __restrict__ hprev,
                                                  __half* __restrict__ hout,
                                                  const unsigned* __restrict__ elmaxU,
                                                  int residual) {
    int gw   = (blockIdx.x * blockDim.x + threadIdx.x) >> 5;
    int lane = threadIdx.x & 31;
    int half = lane >> 4;
    int hl   = lane & 15;
    int n    = gw * 2 + half;
    if (n >= NN) return;
    unsigned hmask = 0xFFFFu << (half * 16);

    int base = g_rowptr[n];
    int deg  = g_rowptr[n + 1] - base;
    float4 er4 = ((const float4*)g_er)[n];
    uint4 Me = *(const uint4*)elmaxU;
    float m0 = lrelu(fdec(Me.x) + er4.x), m1 = lrelu(fdec(Me.y) + er4.y);
    float m2 = lrelu(fdec(Me.z) + er4.z), m3 = lrelu(fdec(Me.w) + er4.w);

    int hh = hl >> 2;    // lane owns features hl*16..hl*16+15 -> head = hl/4
    unsigned psel = (hh & 1) ? 0x3232u : 0x1010u;   // duplicate hi or lo half

    __half2 acc2[8];
#pragma unroll
    for (int i = 0; i < 8; i++) acc2[i] = __float2half2_rn(0.f);
    float ssum = 0.f;

    for (int c = 0; c < deg; c += 16) {
        int rem = deg - c; if (rem > 16) rem = 16;
        int      s_l  = 0;
        unsigned wp01 = 0, wp23 = 0;
        if (hl < rem) {
            s_l = g_esrc[base + c + hl];
            float4 e4 = ((const float4*)g_el)[s_l];
            float wx = __expf(lrelu(e4.x + er4.x) - m0);
            float wy = __expf(lrelu(e4.y + er4.y) - m1);
            float wz = __expf(lrelu(e4.z + er4.z) - m2);
            float ww = __expf(lrelu(e4.w + er4.w) - m3);
            wp01 = h2_bits(__floats2half2_rn(wx, wy));
            wp23 = h2_bits(__floats2half2_rn(wz, ww));
        }
#pragma unroll 4
        for (int k = 0; k < rem; k++) {
            int      s  = __shfl_sync(hmask, s_l,  k, 16);
            unsigned a0 = __shfl_sync(hmask, wp01, k, 16);
            unsigned a1 = __shfl_sync(hmask, wp23, k, 16);
            unsigned wp = (hh < 2) ? a0 : a1;
            unsigned w2b = __byte_perm(wp, wp, psel);
            __half2  w2 = bits_h2(w2b);
            ssum += __low2float(w2);
            const uint4* zr = (const uint4*)(zh + (size_t)s * HD + hl * 16);
            uint4 p0 = zr[0], p1 = zr[1];
            acc2[0] = __hfma2(w2, bits_h2(p0.x), acc2[0]);
            acc2[1] = __hfma2(w2, bits_h2(p0.y), acc2[1]);
            acc2[2] = __hfma2(w2, bits_h2(p0.z), acc2[2]);
            acc2[3] = __hfma2(w2, bits_h2(p0.w), acc2[3]);
            acc2[4] = __hfma2(w2, bits_h2(p1.x), acc2[4]);
            acc2[5] = __hfma2(w2, bits_h2(p1.y), acc2[5]);
            acc2[6] = __hfma2(w2, bits_h2(p1.z), acc2[6]);
            acc2[7] = __hfma2(w2, bits_h2(p1.w), acc2[7]);
        }
    }

    float inv = 1.f / ssum;
    float o16[16];
#pragma unroll
    for (int i = 0; i < 8; i++) {
        float2 f = __half22float2(acc2[i]);
        o16[2*i]   = f.x * inv;
        o16[2*i+1] = f.y * inv;
    }
    size_t ob = (size_t)n * HD + hl * 16;
    if (residual) {
        const uint4* pp = (const uint4*)(hprev + ob);
        uint4 r0 = pp[0], r1 = pp[1];
        unsigned rr[8] = {r0.x, r0.y, r0.z, r0.w, r1.x, r1.y, r1.z, r1.w};
#pragma unroll
        for (int i = 0; i < 8; i++) {
            float2 p = __half22float2(bits_h2(rr[i]));
            o16[2*i]   = elu1(o16[2*i]   + p.x);
            o16[2*i+1] = elu1(o16[2*i+1] + p.y);
        }
    }
#pragma unroll
    for (int i = 0; i < 16; i++) o16[i] = elu1(o16[i]);

    uint4 pk0, pk1;
    __half2 e;
    e = __floats2half2_rn(o16[0],  o16[1]);  pk0.x = h2_bits(e);
    e = __floats2half2_rn(o16[2],  o16[3]);  pk0.y = h2_bits(e);
    e = __floats2half2_rn(o16[4],  o16[5]);  pk0.z = h2_bits(e);
    e = __floats2half2_rn(o16[6],  o16[7]);  pk0.w = h2_bits(e);
    e = __floats2half2_rn(o16[8],  o16[9]);  pk1.x = h2_bits(e);
    e = __floats2half2_rn(o16[10], o16[11]); pk1.y = h2_bits(e);
    e = __floats2half2_rn(o16[12], o16[13]); pk1.z = h2_bits(e);
    e = __floats2half2_rn(o16[14], o16[15]); pk1.w = h2_bits(e);
    *(uint4*)(hout + ob)     = pk0;
    *(uint4*)(hout + ob + 8) = pk1;
}

// ---------------- pooling + classifier (fp16 input) ----------------
__global__ __launch_bounds__(256) void pool_kernel(const __half* __restrict__ h,
                                                   const float* __restrict__ Wc,
                                                   const float* __restrict__ bc,
                                                   float* __restrict__ out) {
    __shared__ float hg[HD];
    int g = blockIdx.x;
    int t = threadIdx.x;
    float s = 0.f;
    const __half* base = h + (size_t)g * NPG * HD + t;
    for (int i = 0; i < NPG; i++) s += __half2float(base[(size_t)i * HD]);
    hg[t] = elu1(s * (1.f / NPG));
    __syncthreads();
    if (t < CC) {
        float acc = bc[t];
        for (int f = 0; f < HD; f++) acc = fmaf(hg[f], Wc[f * CC + t], acc);
        out[g * CC + t] = acc;
    }
}

// ---------------- launch ----------------
extern "C" void kernel_launch(void* const* d_in, const int* in_sizes, int n_in,
                              void* d_out, int out_size) {
    const float* x   = (const float*)d_in[0];
    const int*   src = (const int*)  d_in[1];
    const int*   dst = (const int*)  d_in[2];
    const float* W0  = (const float*)d_in[4];
    const float* al0 = (const float*)d_in[5];
    const float* ar0 = (const float*)d_in[6];
    const float* W1  = (const float*)d_in[7];
    const float* al1 = (const float*)d_in[8];
    const float* ar1 = (const float*)d_in[9];
    const float* W2  = (const float*)d_in[10];
    const float* al2 = (const float*)d_in[11];
    const float* ar2 = (const float*)d_in[12];
    const float* Wc  = (const float*)d_in[13];
    const float* bc  = (const float*)d_in[14];
    float* out = (float*)d_out;

    __half *zh, *h16, *bf16;
    unsigned* emx;
    cudaGetSymbolAddress((void**)&zh,   g_zh);
    cudaGetSymbolAddress((void**)&h16,  g_h16);
    cudaGetSymbolAddress((void**)&bf16, g_bf16);
    cudaGetSymbolAddress((void**)&emx,  g_elmaxU);
    __half* h0 = h16;                 // ping
    __half* h1 = h16 + (size_t)NN * HD;   // pong

    cudaFuncSetAttribute(gemm_mma_kernel,
                         cudaFuncAttributeMaxDynamicSharedMemorySize, SMEM_GEMM);

    // fork CSR build onto a side stream, overlapped with conv + layer-0 GEMM
    cudaStream_t s2;
    cudaStreamCreateWithFlags(&s2, cudaStreamNonBlocking);
    cudaEvent_t evFork, evJoin;
    cudaEventCreateWithFlags(&evFork, cudaEventDisableTiming);
    cudaEventCreateWithFlags(&evJoin, cudaEventDisableTiming);

    cudaEventRecord(evFork, 0);
    cudaStreamWaitEvent(s2, evFork, 0);
    zero_deg_kernel<<<(NN + 255) / 256, 256, 0, s2>>>();
    hist_kernel<<<(EE + 255) / 256, 256, 0, s2>>>(dst);
    scan_kernel<<<1, 512, 0, s2>>>();
    scatter_kernel<<<(EE + 255) / 256, 256, 0, s2>>>(src, dst);
    cudaEventRecord(evJoin, s2);

    // main stream: single conversion kernel (x -> h0, all W, elmax reset)
    int convN = NN * 128 / 4 + (128 + 512) * HD;
    conv_kernel<<<(convN + 255) / 256, 256>>>(x, W0, W1, W2);

    dim3 ggrid(NN / 64, 2);

    // layer 0: A = h0 (x fp16, K=128); out -> h1
    gemm_mma_kernel<<<ggrid, 256, SMEM_GEMM>>>(h0, bf16, zh,
                                               emx + 0, al0, ar0, 128);
    cudaStreamWaitEvent(0, evJoin, 0);   // CSR ready before first agg
    agg_kernel<<<NN / 16, 256>>>(zh, (const __half*)nullptr, h1, emx + 0, 0);

    // layer 1: A = h1; residual h1; out -> h0
    gemm_mma_kernel<<<ggrid, 256, SMEM_GEMM>>>(h1, bf16 + HD * HD, zh,
                                               emx + 4, al1, ar1, 256);
    agg_kernel<<<NN / 16, 256>>>(zh, h1, h0, emx + 4, 1);

    // layer 2: A = h0; residual h0; out -> h1
    gemm_mma_kernel<<<ggrid, 256, SMEM_GEMM>>>(h0, bf16 + 2 * HD * HD, zh,
                                               emx + 8, al2, ar2, 256);
    agg_kernel<<<NN / 16, 256>>>(zh, h0, h1, emx + 8, 1);

    pool_kernel<<<GG, 256>>>(h1, Wc, bc, out);
}

// round 16
// speedup vs baseline: 1.9904x; 1.0807x over previous
#include <cuda_runtime.h>
#include <cuda_bf16.h>
#include <cuda_fp16.h>
#include <math.h>
#include <stdint.h>

#define NN 20480
#define EE 327680
#define GG 64
#define HD 256     // H*D
#define HH 4
#define DD 64
#define CC 10
#define NPG (NN/GG)

// ---------------- scratch (static device globals; no allocation) ----------------
__device__ __half g_zh[NN*HD];               // z in fp16 (agg gather operand)
__device__ __half g_h16[2][NN*HD];           // activation ping-pong (fp16)
__device__ float g_el[NN*HH];
__device__ float g_er[NN*HH];
__device__ unsigned g_elmaxU[3*HH];          // encoded per-head el max, per layer
__device__ int   g_deg[NN];
__device__ int   g_rowptr[NN+1];
__device__ int   g_cursor[NN];
__device__ int   g_esrc[EE];
__device__ __half g_bf16[3][HD*HD];          // W per layer: [K][256] fp16

__device__ __forceinline__ float lrelu(float x) { return x > 0.f ? x : 0.2f * x; }
// fast ELU: exp(x)-1 via MUFU.EX2; cancellation error ~1e-7 abs (far under budget)
__device__ __forceinline__ float elu1 (float x) { return x > 0.f ? x : __expf(x) - 1.f; }

// monotone float<->uint encoding for atomicMax on floats
__device__ __forceinline__ unsigned fenc(float f) {
    unsigned u = __float_as_uint(f);
    return (u & 0x80000000u) ? ~u : (u | 0x80000000u);
}
__device__ __forceinline__ float fdec(unsigned u) {
    return (u & 0x80000000u) ? __uint_as_float(u & 0x7fffffffu) : __uint_as_float(~u);
}
__device__ __forceinline__ unsigned h2_bits(__half2 h) {
    return *reinterpret_cast<unsigned*>(&h);
}
__device__ __forceinline__ __half2 bits_h2(unsigned u) {
    return *reinterpret_cast<__half2*>(&u);
}

__device__ __forceinline__ uint32_t smem_u32(const void* p) {
    uint32_t a;
    asm("{ .reg .u64 t; cvta.to.shared.u64 t, %1; cvt.u32.u64 %0, t; }" : "=r"(a) : "l"(p));
    return a;
}
__device__ __forceinline__ void ldmat4(uint32_t* r, uint32_t a) {
    asm volatile("ldmatrix.sync.aligned.m8n8.x4.shared.b16 {%0,%1,%2,%3}, [%4];"
        : "=r"(r[0]), "=r"(r[1]), "=r"(r[2]), "=r"(r[3]) : "r"(a));
}
__device__ __forceinline__ void ldmat4t(uint32_t* r, uint32_t a) {
    asm volatile("ldmatrix.sync.aligned.m8n8.x4.trans.shared.b16 {%0,%1,%2,%3}, [%4];"
        : "=r"(r[0]), "=r"(r[1]), "=r"(r[2]), "=r"(r[3]) : "r"(a));
}
__device__ __forceinline__ void mma16816h(float* c, const uint32_t* a, const uint32_t* b) {
    asm volatile(
        "mma.sync.aligned.m16n8k16.row.col.f32.f16.f16.f32 "
        "{%0,%1,%2,%3}, {%4,%5,%6,%7}, {%8,%9}, {%0,%1,%2,%3};"
        : "+f"(c[0]), "+f"(c[1]), "+f"(c[2]), "+f"(c[3])
        : "r"(a[0]), "r"(a[1]), "r"(a[2]), "r"(a[3]), "r"(b[0]), "r"(b[1]));
}
#define CP16(s, g) asm volatile("cp.async.cg.shared.global [%0], [%1], 16;" \
    :: "r"(s), "l"(__cvta_generic_to_global(g)))
#define CP_COMMIT() asm volatile("cp.async.commit_group;" ::: "memory")
#define CP_WAIT0()  asm volatile("cp.async.wait_group 0;" ::: "memory")
#define CP_WAIT1()  asm volatile("cp.async.wait_group 1;" ::: "memory")

// ---------------- CSR build ----------------
__global__ void zero_deg_kernel() {
    int i = blockIdx.x * blockDim.x + threadIdx.x;
    if (i < NN) g_deg[i] = 0;
}
__global__ void hist_kernel(const int* __restrict__ dst) {
    int i = blockIdx.x * blockDim.x + threadIdx.x;
    if (i < EE) atomicAdd(&g_deg[dst[i]], 1);
}
__global__ void scan_kernel() {
    __shared__ int part[512];
    const int CH = NN / 512;
    int t = threadIdx.x;
    int s = 0;
    for (int i = 0; i < CH; i++) s += g_deg[t*CH + i];
    part[t] = s;
    __syncthreads();
    if (t == 0) {
        int r = 0;
        for (int i = 0; i < 512; i++) { int v = part[i]; part[i] = r; r += v; }
        g_rowptr[NN] = r;
    }
    __syncthreads();
    int run = part[t];
    for (int i = 0; i < CH; i++) {
        int idx = t*CH + i;
        g_rowptr[idx] = run;
        g_cursor[idx] = run;
        run += g_deg[idx];
    }
}
__global__ void scatter_kernel(const int* __restrict__ src, const int* __restrict__ dst) {
    int i = blockIdx.x * blockDim.x + threadIdx.x;
    if (i < EE) {
        int p = atomicAdd(&g_cursor[dst[i]], 1);
        g_esrc[p] = src[i];
    }
}

// ---------------- conversions: x -> fp16 (ping buffer 0), W0..W2 -> fp16, elmax reset ----------------
__global__ void conv_kernel(const float* __restrict__ x,
                            const float* __restrict__ W0,
                            const float* __restrict__ W1,
                            const float* __restrict__ W2) {
    int i = blockIdx.x * blockDim.x + threadIdx.x;
    if (blockIdx.x == 0 && threadIdx.x < 3 * HH) g_elmaxU[threadIdx.x] = 0u;
    const int NX4 = NN * 128 / 4;   // x as float4
    if (i < NX4) {
        float4 v = ((const float4*)x)[i];
        ((__half2*)g_h16[0])[2*i]   = __floats2half2_rn(v.x, v.y);
        ((__half2*)g_h16[0])[2*i+1] = __floats2half2_rn(v.z, v.w);
        return;
    }
    int j = i - NX4;
    const float* B; int layer, off;
    if (j < 128 * HD)           { B = W0; layer = 0; off = j; }
    else if (j < (128+256)*HD)  { B = W1; layer = 1; off = j - 128 * HD; }
    else if (j < (128+512)*HD)  { B = W2; layer = 2; off = j - (128+256) * HD; }
    else return;
    g_bf16[layer][off] = __float2half(B[off]);
}

// ---------------- fp16 mma.sync GEMM + fused attn projections + fused el-max ----------------
// CTA 64(M)x128(N), 8 warps (warp = 16x64), K chunks of 32, cp.async double buffer.
#define ARB 80        // A smem row bytes (32 fp16 = 64B + pad)
#define BRB 272       // B smem row bytes (128 fp16 = 256B + pad)
#define S_B   5120    // 64 rows * ARB
#define BUF   13824   // S_B + 32*BRB
#define SMEM_GEMM (2*BUF)

__global__ __launch_bounds__(256, 3) void gemm_mma_kernel(
    const __half* __restrict__ A, const __half* __restrict__ B,
    __half* __restrict__ Zh, unsigned* __restrict__ elmaxU,
    const float* __restrict__ al, const float* __restrict__ ar, int K) {
    extern __shared__ char sm[];
    uint32_t sb = smem_u32(sm);
    int tid = threadIdx.x, lane = tid & 31, wid = tid >> 5;
    int wm = wid & 3, wn = wid >> 2;
    int bm = blockIdx.x * 64, bn = blockIdx.y * 128;

    float acc[8][4];
#pragma unroll
    for (int j = 0; j < 8; j++)
#pragma unroll
        for (int q = 0; q < 4; q++) acc[j][q] = 0.f;

    auto issue = [&](int c, int buf) {
        int k0 = c * 32;
        uint32_t s0 = sb + buf * BUF;
        {
            int arow = tid >> 2, ach = tid & 3;
            const __half* ga = A + (size_t)(bm + arow) * K + k0 + ach * 8;
            CP16(s0 + arow * ARB + ach * 16, ga);
        }
#pragma unroll
        for (int r = 0; r < 2; r++) {
            int idx  = tid + r * 256;
            int brow = idx >> 4, bch = idx & 15;
            const __half* gb = B + (size_t)(k0 + brow) * HD + bn + bch * 8;
            CP16(s0 + S_B + brow * BRB + bch * 16, gb);
        }
    };

    auto compute = [&](int buf) {
        uint32_t s0 = sb + buf * BUF;
#pragma unroll
        for (int ks = 0; ks < 32; ks += 16) {
            uint32_t ah[4];
            {
                int row = wm * 16 + (lane & 15);
                uint32_t ad = s0 + row * ARB + (ks + (lane >> 4) * 8) * 2;
                ldmat4(ah, ad);
            }
#pragma unroll
            for (int jj = 0; jj < 4; jj++) {
                int krow = ks + (lane & 15);
                int ncol = wn * 64 + jj * 16 + (lane >> 4) * 8;
                uint32_t bd = s0 + S_B + krow * BRB + ncol * 2;
                uint32_t bh[4];
                ldmat4t(bh, bd);
                mma16816h(acc[2*jj],   ah, bh);
                mma16816h(acc[2*jj+1], ah, bh + 2);
            }
        }
    };

    int nch = K >> 5;
    issue(0, 0);
    CP_COMMIT();
    for (int c = 0; c < nch; c++) {
        if (c + 1 < nch) {
            issue(c + 1, (c + 1) & 1);
            CP_COMMIT();
            CP_WAIT1();
        } else {
            CP_WAIT0();
        }
        __syncthreads();
        compute(c & 1);
        __syncthreads();
    }

    int grp = lane >> 2, tig = lane & 3;

    // ---- store z as fp16 (rows bm+wm*16+grp and +8) ----
    {
        int rbase = bm + wm * 16 + grp;
#pragma unroll
        for (int j = 0; j < 8; j++) {
            int col = bn + wn * 64 + j * 8 + tig * 2;
            __half2 h0 = __floats2half2_rn(acc[j][0], acc[j][1]);
            __half2 h1 = __floats2half2_rn(acc[j][2], acc[j][3]);
            *(__half2*)(Zh + (size_t)rbase * HD + col)       = h0;
            *(__half2*)(Zh + (size_t)(rbase + 8) * HD + col) = h1;
        }
    }

    {   // ---- fused el/er for head hglob + global el-max atomic ----
        int hglob = (bn >> 6) + wn;
        const float* alh = al + hglob * DD;
        const float* arh = ar + hglob * DD;
        float alv[16], arv[16];
#pragma unroll
        for (int j = 0; j < 8; j++) {
            int cw = j * 8 + tig * 2;
            alv[2*j]   = alh[cw];   alv[2*j+1] = alh[cw+1];
            arv[2*j]   = arh[cw];   arv[2*j+1] = arh[cw+1];
        }
        float el1 = 0.f, er1 = 0.f, el2 = 0.f, er2 = 0.f;
#pragma unroll
        for (int j = 0; j < 8; j++) {
            el1 = fmaf(acc[j][0], alv[2*j], fmaf(acc[j][1], alv[2*j+1], el1));
            er1 = fmaf(acc[j][0], arv[2*j], fmaf(acc[j][1], arv[2*j+1], er1));
            el2 = fmaf(acc[j][2], alv[2*j], fmaf(acc[j][3], alv[2*j+1], el2));
            er2 = fmaf(acc[j][2], arv[2*j], fmaf(acc[j][3], arv[2*j+1], er2));
        }
#pragma unroll
        for (int o = 1; o <= 2; o <<= 1) {
            el1 += __shfl_xor_sync(0xffffffffu, el1, o);
            er1 += __shfl_xor_sync(0xffffffffu, er1, o);
            el2 += __shfl_xor_sync(0xffffffffu, el2, o);
            er2 += __shfl_xor_sync(0xffffffffu, er2, o);
        }
        if (tig == 0) {
            int r1 = bm + wm * 16 + grp;
            g_el[r1 * HH + hglob]       = el1;
            g_er[r1 * HH + hglob]       = er1;
            g_el[(r1 + 8) * HH + hglob] = el2;
            g_er[(r1 + 8) * HH + hglob] = er2;
        }
        float wmax = fmaxf(el1, el2);
#pragma unroll
        for (int o = 16; o >= 4; o >>= 1)
            wmax = fmaxf(wmax, __shfl_xor_sync(0xffffffffu, wmax, o));
        if (lane == 0) atomicMax(&elmaxU[hglob], fenc(wmax));
    }
}

// ---------------- per-node edge-softmax aggregation ----------------
// 2 nodes per warp; each half-warp (16 lanes) handles one node, lane owns 16 features.
// fp16 z gather + packed half2 accumulation (HFMA2); ssum in fp32.
__global__ __launch_bounds__(256) void agg_kernel(const __half* __restrict__ zh,
                                                  const __half* __restrict__ hprev,
                                                  __half* __restrict__ hout,
                                                  const unsigned* __restrict__ elmaxU,
                                                  int residual) {
    int gw   = (blockIdx.x * blockDim.x + threadIdx.x) >> 5;
    int lane = threadIdx.x & 31;
    int half = lane >> 4;
    int hl   = lane & 15;
    int n    = gw * 2 + half;
    if (n >= NN) return;
    unsigned hmask = 0xFFFFu << (half * 16);

    int base = g_rowptr[n];
    int deg  = g_rowptr[n + 1] - base;
    float4 er4 = ((const float4*)g_er)[n];
    uint4 Me = *(const uint4*)elmaxU;
    float m0 = lrelu(fdec(Me.x) + er4.x), m1 = lrelu(fdec(Me.y) + er4.y);
    float m2 = lrelu(fdec(Me.z) + er4.z), m3 = lrelu(fdec(Me.w) + er4.w);

    int hh = hl >> 2;    // lane owns features hl*16..hl*16+15 -> head = hl/4
    unsigned psel = (hh & 1) ? 0x3232u : 0x1010u;   // duplicate hi or lo half

    __half2 acc2[8];
#pragma unroll
    for (int i = 0; i < 8; i++) acc2[i] = __float2half2_rn(0.f);
    float ssum = 0.f;

    for (int c = 0; c < deg; c += 16) {
        int rem = deg - c; if (rem > 16) rem = 16;
        int      s_l  = 0;
        unsigned wp01 = 0, wp23 = 0;
        if (hl < rem) {
            s_l = g_esrc[base + c + hl];
            float4 e4 = ((const float4*)g_el)[s_l];
            float wx = __expf(lrelu(e4.x + er4.x) - m0);
            float wy = __expf(lrelu(e4.y + er4.y) - m1);
            float wz = __expf(lrelu(e4.z + er4.z) - m2);
            float ww = __expf(lrelu(e4.w + er4.w) - m3);
            wp01 = h2_bits(__floats2half2_rn(wx, wy));
            wp23 = h2_bits(__floats2half2_rn(wz, ww));
        }
#pragma unroll 4
        for (int k = 0; k < rem; k++) {
            int      s  = __shfl_sync(hmask, s_l,  k, 16);
            unsigned a0 = __shfl_sync(hmask, wp01, k, 16);
            unsigned a1 = __shfl_sync(hmask, wp23, k, 16);
            unsigned wp = (hh < 2) ? a0 : a1;
            unsigned w2b = __byte_perm(wp, wp, psel);
            __half2  w2 = bits_h2(w2b);
            ssum += __low2float(w2);
            const uint4* zr = (const uint4*)(zh + (size_t)s * HD + hl * 16);
            uint4 p0 = zr[0], p1 = zr[1];
            acc2[0] = __hfma2(w2, bits_h2(p0.x), acc2[0]);
            acc2[1] = __hfma2(w2, bits_h2(p0.y), acc2[1]);
            acc2[2] = __hfma2(w2, bits_h2(p0.z), acc2[2]);
            acc2[3] = __hfma2(w2, bits_h2(p0.w), acc2[3]);
            acc2[4] = __hfma2(w2, bits_h2(p1.x), acc2[4]);
            acc2[5] = __hfma2(w2, bits_h2(p1.y), acc2[5]);
            acc2[6] = __hfma2(w2, bits_h2(p1.z), acc2[6]);
            acc2[7] = __hfma2(w2, bits_h2(p1.w), acc2[7]);
        }
    }

    float inv = 1.f / ssum;
    float o16[16];
#pragma unroll
    for (int i = 0; i < 8; i++) {
        float2 f = __half22float2(acc2[i]);
        o16[2*i]   = f.x * inv;
        o16[2*i+1] = f.y * inv;
    }
    size_t ob = (size_t)n * HD + hl * 16;
    if (residual) {
        const uint4* pp = (const uint4*)(hprev + ob);
        uint4 r0 = pp[0], r1 = pp[1];
        unsigned rr[8] = {r0.x, r0.y, r0.z, r0.w, r1.x, r1.y, r1.z, r1.w};
#pragma unroll
        for (int i = 0; i < 8; i++) {
            float2 p = __half22float2(bits_h2(rr[i]));
            o16[2*i]   = elu1(o16[2*i]   + p.x);
            o16[2*i+1] = elu1(o16[2*i+1] + p.y);
        }
    }
#pragma unroll
    for (int i = 0; i < 16; i++) o16[i] = elu1(o16[i]);

    uint4 pk0, pk1;
    __half2 e;
    e = __floats2half2_rn(o16[0],  o16[1]);  pk0.x = h2_bits(e);
    e = __floats2half2_rn(o16[2],  o16[3]);  pk0.y = h2_bits(e);
    e = __floats2half2_rn(o16[4],  o16[5]);  pk0.z = h2_bits(e);
    e = __floats2half2_rn(o16[6],  o16[7]);  pk0.w = h2_bits(e);
    e = __floats2half2_rn(o16[8],  o16[9]);  pk1.x = h2_bits(e);
    e = __floats2half2_rn(o16[10], o16[11]); pk1.y = h2_bits(e);
    e = __floats2half2_rn(o16[12], o16[13]); pk1.z = h2_bits(e);
    e = __floats2half2_rn(o16[14], o16[15]); pk1.w = h2_bits(e);
    *(uint4*)(hout + ob)     = pk0;
    *(uint4*)(hout + ob + 8) = pk1;
}

// ---------------- pooling + classifier (fp16 input) ----------------
__global__ __launch_bounds__(256) void pool_kernel(const __half* __restrict__ h,
                                                   const float* __restrict__ Wc,
                                                   const float* __restrict__ bc,
                                                   float* __restrict__ out) {
    __shared__ float hg[HD];
    int g = blockIdx.x;
    int t = threadIdx.x;
    float s = 0.f;
    const __half* base = h + (size_t)g * NPG * HD + t;
    for (int i = 0; i < NPG; i++) s += __half2float(base[(size_t)i * HD]);
    hg[t] = elu1(s * (1.f / NPG));
    __syncthreads();
    if (t < CC) {
        float acc = bc[t];
        for (int f = 0; f < HD; f++) acc = fmaf(hg[f], Wc[f * CC + t], acc);
        out[g * CC + t] = acc;
    }
}

// ---------------- launch ----------------
extern "C" void kernel_launch(void* const* d_in, const int* in_sizes, int n_in,
                              void* d_out, int out_size) {
    const float* x   = (const float*)d_in[0];
    const int*   src = (const int*)  d_in[1];
    const int*   dst = (const int*)  d_in[2];
    const float* W0  = (const float*)d_in[4];
    const float* al0 = (const float*)d_in[5];
    const float* ar0 = (const float*)d_in[6];
    const float* W1  = (const float*)d_in[7];
    const float* al1 = (const float*)d_in[8];
    const float* ar1 = (const float*)d_in[9];
    const float* W2  = (const float*)d_in[10];
    const float* al2 = (const float*)d_in[11];
    const float* ar2 = (const float*)d_in[12];
    const float* Wc  = (const float*)d_in[13];
    const float* bc  = (const float*)d_in[14];
    float* out = (float*)d_out;

    __half *zh, *h16, *bf16;
    unsigned* emx;
    cudaGetSymbolAddress((void**)&zh,   g_zh);
    cudaGetSymbolAddress((void**)&h16,  g_h16);
    cudaGetSymbolAddress((void**)&bf16, g_bf16);
    cudaGetSymbolAddress((void**)&emx,  g_elmaxU);
    __half* h0 = h16;                     // ping
    __half* h1 = h16 + (size_t)NN * HD;   // pong

    cudaFuncSetAttribute(gemm_mma_kernel,
                         cudaFuncAttributeMaxDynamicSharedMemorySize, SMEM_GEMM);

    // fork CSR build onto a side stream, overlapped with conv + layer-0 GEMM
    cudaStream_t s2;
    cudaStreamCreateWithFlags(&s2, cudaStreamNonBlocking);
    cudaEvent_t evFork, evJoin;
    cudaEventCreateWithFlags(&evFork, cudaEventDisableTiming);
    cudaEventCreateWithFlags(&evJoin, cudaEventDisableTiming);

    cudaEventRecord(evFork, 0);
    cudaStreamWaitEvent(s2, evFork, 0);
    zero_deg_kernel<<<(NN + 255) / 256, 256, 0, s2>>>();
    hist_kernel<<<(EE + 255) / 256, 256, 0, s2>>>(dst);
    scan_kernel<<<1, 512, 0, s2>>>();
    scatter_kernel<<<(EE + 255) / 256, 256, 0, s2>>>(src, dst);
    cudaEventRecord(evJoin, s2);

    // main stream: single conversion kernel (x -> h0, all W, elmax reset)
    int convN = NN * 128 / 4 + (128 + 512) * HD;
    conv_kernel<<<(convN + 255) / 256, 256>>>(x, W0, W1, W2);

    dim3 ggrid(NN / 64, 2);

    // layer 0: A = h0 (x fp16, K=128); out -> h1
    gemm_mma_kernel<<<ggrid, 256, SMEM_GEMM>>>(h0, bf16, zh,
                                               emx + 0, al0, ar0, 128);
    cudaStreamWaitEvent(0, evJoin, 0);   // CSR ready before first agg
    agg_kernel<<<NN / 16, 256>>>(zh, (const __half*)nullptr, h1, emx + 0, 0);

    // layer 1: A = h1; residual h1; out -> h0
    gemm_mma_kernel<<<ggrid, 256, SMEM_GEMM>>>(h1, bf16 + HD * HD, zh,
                                               emx + 4, al1, ar1, 256);
    agg_kernel<<<NN / 16, 256>>>(zh, h1, h0, emx + 4, 1);

    // layer 2: A = h0; residual h0; out -> h1
    gemm_mma_kernel<<<ggrid, 256, SMEM_GEMM>>>(h0, bf16 + 2 * HD * HD, zh,
                                               emx + 8, al2, ar2, 256);
    agg_kernel<<<NN / 16, 256>>>(zh, h0, h1, emx + 8, 1);

    pool_kernel<<<GG, 256>>>(h1, Wc, bc, out);
}